// round 1
// baseline (speedup 1.0000x reference)
#include <cuda_runtime.h>
#include <math.h>

#define DMODEL 1024
#define NHEADS 16
#define DK     64
#define BATCH  4
#define SEQ    2048
#define MTOT   (BATCH*SEQ)   // 8192

// Scratch (static device globals — allocation-free)
__device__ float g_Q[(size_t)MTOT * DMODEL];     // [B,H,S,DK] layout
__device__ float g_K[(size_t)MTOT * DMODEL];
__device__ float g_V[(size_t)MTOT * DMODEL];
__device__ float g_attn[(size_t)MTOT * DMODEL];  // [B,S,H*DK] layout

// ---------------------------------------------------------------------------
// Fused QKV projection: C = x[8192,1024] @ W[1024,1024]^T + b
// 128x128 block tile, BK=16, 256 threads, 8x8 per thread.
// blockIdx.z: 0->Q, 1->K, 2->V ; output scattered to [B,H,S,DK].
// ---------------------------------------------------------------------------
__global__ __launch_bounds__(256) void qkv_kernel(
    const float* __restrict__ x,
    const float* __restrict__ Wq, const float* __restrict__ bq,
    const float* __restrict__ Wk, const float* __restrict__ bk,
    const float* __restrict__ Wv, const float* __restrict__ bv)
{
    __shared__ float As[16][128];
    __shared__ float Bs[16][128];

    const int z = blockIdx.z;
    const float* W    = (z == 0) ? Wq : ((z == 1) ? Wk : Wv);
    const float* bias = (z == 0) ? bq : ((z == 1) ? bk : bv);
    float* out        = (z == 0) ? g_Q : ((z == 1) ? g_K : g_V);

    const int m0 = blockIdx.x * 128;
    const int n0 = blockIdx.y * 128;
    const int tid = threadIdx.x;
    const int tx = tid & 15;        // 0..15 -> 8 cols each
    const int ty = tid >> 4;        // 0..15 -> 8 rows each

    float acc[8][8];
#pragma unroll
    for (int i = 0; i < 8; i++)
#pragma unroll
        for (int j = 0; j < 8; j++) acc[i][j] = 0.f;

    for (int k0 = 0; k0 < DMODEL; k0 += 16) {
#pragma unroll
        for (int r = 0; r < 2; r++) {
            int f   = tid + 256 * r;     // 0..511 float4 slots
            int row = f >> 2;            // 0..127
            int kc  = (f & 3) << 2;      // 0,4,8,12
            float4 a = *reinterpret_cast<const float4*>(&x[(size_t)(m0 + row) * DMODEL + k0 + kc]);
            As[kc + 0][row] = a.x; As[kc + 1][row] = a.y;
            As[kc + 2][row] = a.z; As[kc + 3][row] = a.w;
            float4 b = *reinterpret_cast<const float4*>(&W[(size_t)(n0 + row) * DMODEL + k0 + kc]);
            Bs[kc + 0][row] = b.x; Bs[kc + 1][row] = b.y;
            Bs[kc + 2][row] = b.z; Bs[kc + 3][row] = b.w;
        }
        __syncthreads();

#pragma unroll
        for (int k = 0; k < 16; k++) {
            float4 a0 = *reinterpret_cast<const float4*>(&As[k][ty * 8]);
            float4 a1 = *reinterpret_cast<const float4*>(&As[k][ty * 8 + 4]);
            float4 b0 = *reinterpret_cast<const float4*>(&Bs[k][tx * 8]);
            float4 b1 = *reinterpret_cast<const float4*>(&Bs[k][tx * 8 + 4]);
            float av[8] = {a0.x, a0.y, a0.z, a0.w, a1.x, a1.y, a1.z, a1.w};
            float bv2[8] = {b0.x, b0.y, b0.z, b0.w, b1.x, b1.y, b1.z, b1.w};
#pragma unroll
            for (int i = 0; i < 8; i++)
#pragma unroll
                for (int j = 0; j < 8; j++)
                    acc[i][j] = fmaf(av[i], bv2[j], acc[i][j]);
        }
        __syncthreads();
    }

    // Write with bias, scattered to [B,H,S,DK]
#pragma unroll
    for (int i = 0; i < 8; i++) {
        int m = m0 + ty * 8 + i;
        int b = m >> 11;            // /SEQ
        int s = m & (SEQ - 1);
#pragma unroll
        for (int j = 0; j < 8; j++) {
            int n = n0 + tx * 8 + j;
            int h = n >> 6;         // /DK
            int d = n & (DK - 1);
            out[(((size_t)(b * NHEADS + h)) * SEQ + s) * DK + d] = acc[i][j] + bias[n];
        }
    }
}

// ---------------------------------------------------------------------------
// Output projection: out = g_attn[8192,1024] @ Wo^T + bo (row-major output)
// ---------------------------------------------------------------------------
__global__ __launch_bounds__(256) void proj_kernel(
    const float* __restrict__ Wo, const float* __restrict__ bo,
    float* __restrict__ out)
{
    __shared__ float As[16][128];
    __shared__ float Bs[16][128];

    const int m0 = blockIdx.x * 128;
    const int n0 = blockIdx.y * 128;
    const int tid = threadIdx.x;
    const int tx = tid & 15;
    const int ty = tid >> 4;

    float acc[8][8];
#pragma unroll
    for (int i = 0; i < 8; i++)
#pragma unroll
        for (int j = 0; j < 8; j++) acc[i][j] = 0.f;

    for (int k0 = 0; k0 < DMODEL; k0 += 16) {
#pragma unroll
        for (int r = 0; r < 2; r++) {
            int f   = tid + 256 * r;
            int row = f >> 2;
            int kc  = (f & 3) << 2;
            float4 a = *reinterpret_cast<const float4*>(&g_attn[(size_t)(m0 + row) * DMODEL + k0 + kc]);
            As[kc + 0][row] = a.x; As[kc + 1][row] = a.y;
            As[kc + 2][row] = a.z; As[kc + 3][row] = a.w;
            float4 b = *reinterpret_cast<const float4*>(&Wo[(size_t)(n0 + row) * DMODEL + k0 + kc]);
            Bs[kc + 0][row] = b.x; Bs[kc + 1][row] = b.y;
            Bs[kc + 2][row] = b.z; Bs[kc + 3][row] = b.w;
        }
        __syncthreads();

#pragma unroll
        for (int k = 0; k < 16; k++) {
            float4 a0 = *reinterpret_cast<const float4*>(&As[k][ty * 8]);
            float4 a1 = *reinterpret_cast<const float4*>(&As[k][ty * 8 + 4]);
            float4 b0 = *reinterpret_cast<const float4*>(&Bs[k][tx * 8]);
            float4 b1 = *reinterpret_cast<const float4*>(&Bs[k][tx * 8 + 4]);
            float av[8] = {a0.x, a0.y, a0.z, a0.w, a1.x, a1.y, a1.z, a1.w};
            float bv2[8] = {b0.x, b0.y, b0.z, b0.w, b1.x, b1.y, b1.z, b1.w};
#pragma unroll
            for (int i = 0; i < 8; i++)
#pragma unroll
                for (int j = 0; j < 8; j++)
                    acc[i][j] = fmaf(av[i], bv2[j], acc[i][j]);
        }
        __syncthreads();
    }

#pragma unroll
    for (int i = 0; i < 8; i++) {
        int m = m0 + ty * 8 + i;
#pragma unroll
        for (int j = 0; j < 8; j++) {
            int n = n0 + tx * 8 + j;
            out[(size_t)m * DMODEL + n] = acc[i][j] + bo[n];
        }
    }
}

// ---------------------------------------------------------------------------
// Causal flash attention. Grid: (qt=32, bh=64). Block: 256 threads.
// Tiles of 64 queries x 64 keys, d_k=64. Online softmax.
// Dynamic smem: Qs[64][64] (d-major), Ks[64][64] (d-major), Vs[64][64],
//               Ss[64][65], m/l/fac[64].
// ---------------------------------------------------------------------------
#define SPT 65
#define ATTN_SMEM ((3*64*64 + 64*SPT + 3*64) * sizeof(float))

__global__ __launch_bounds__(256) void attn_kernel()
{
    extern __shared__ float sm[];
    float* Qs   = sm;                 // [d][r] : 4096
    float* Ks   = sm + 4096;          // [d][c] : 4096
    float* Vs   = sm + 8192;          // [c][d] : 4096
    float* Ss   = sm + 12288;         // [r][c] stride 65 : 4160
    float* m_i  = sm + 12288 + 64 * SPT;
    float* l_i  = m_i + 64;
    float* fac  = l_i + 64;

    const int qt  = blockIdx.x;       // 0..31
    const int bh  = blockIdx.y;       // 0..63
    const int q0  = qt * 64;
    const size_t base = (size_t)bh * SEQ * DK;

    const int tid = threadIdx.x;
    const int tx  = tid & 15;         // cols (d or key) 4*tx
    const int ty  = tid >> 4;         // rows 4*ty

    // Load Q tile transposed (d-major), pre-scaled by 1/sqrt(dk)
    const float scale = 0.125f;       // 1/sqrt(64)
#pragma unroll
    for (int it = 0; it < 16; it++) {
        int e = tid + 256 * it;       // 0..4095
        int r = e >> 6, d = e & 63;
        Qs[d * 64 + r] = g_Q[base + (size_t)(q0 + r) * DK + d] * scale;
    }
    if (tid < 64) { m_i[tid] = -3.0e38f; l_i[tid] = 0.f; }

    float o[4][4];
#pragma unroll
    for (int i = 0; i < 4; i++)
#pragma unroll
        for (int j = 0; j < 4; j++) o[i][j] = 0.f;

    __syncthreads();

    for (int kt = 0; kt <= qt; kt++) {
        const int k0 = kt * 64;
        // Load K (d-major) and V (natural)
#pragma unroll
        for (int it = 0; it < 16; it++) {
            int e = tid + 256 * it;
            int c = e >> 6, d = e & 63;
            Ks[d * 64 + c] = g_K[base + (size_t)(k0 + c) * DK + d];
            Vs[e]          = g_V[base + (size_t)k0 * DK + e];
        }
        __syncthreads();

        // S = Q @ K^T  (pre-scaled)
        float sacc[4][4];
#pragma unroll
        for (int i = 0; i < 4; i++)
#pragma unroll
            for (int j = 0; j < 4; j++) sacc[i][j] = 0.f;

#pragma unroll 8
        for (int d = 0; d < 64; d++) {
            float4 qv = *reinterpret_cast<const float4*>(&Qs[d * 64 + ty * 4]);
            float4 kv = *reinterpret_cast<const float4*>(&Ks[d * 64 + tx * 4]);
            float qa[4] = {qv.x, qv.y, qv.z, qv.w};
            float ka[4] = {kv.x, kv.y, kv.z, kv.w};
#pragma unroll
            for (int i = 0; i < 4; i++)
#pragma unroll
                for (int j = 0; j < 4; j++)
                    sacc[i][j] = fmaf(qa[i], ka[j], sacc[i][j]);
        }

        // Causal mask on the diagonal tile
        if (kt == qt) {
#pragma unroll
            for (int i = 0; i < 4; i++)
#pragma unroll
                for (int j = 0; j < 4; j++)
                    if (tx * 4 + j > ty * 4 + i) sacc[i][j] = -1.0e30f;
        }
#pragma unroll
        for (int i = 0; i < 4; i++)
#pragma unroll
            for (int j = 0; j < 4; j++)
                Ss[(ty * 4 + i) * SPT + tx * 4 + j] = sacc[i][j];
        __syncthreads();

        // Per-row online softmax (threads 0..63, one row each)
        if (tid < 64) {
            float* row = &Ss[tid * SPT];
            float mx = m_i[tid];
#pragma unroll 8
            for (int c = 0; c < 64; c++) mx = fmaxf(mx, row[c]);
            float f = __expf(m_i[tid] - mx);
            float sum = 0.f;
#pragma unroll 8
            for (int c = 0; c < 64; c++) {
                float p = __expf(row[c] - mx);
                row[c] = p;
                sum += p;
            }
            l_i[tid] = l_i[tid] * f + sum;
            m_i[tid] = mx;
            fac[tid] = f;
        }
        __syncthreads();

        // O = O*fac + P @ V
        float fr[4];
#pragma unroll
        for (int i = 0; i < 4; i++) fr[i] = fac[ty * 4 + i];
#pragma unroll
        for (int i = 0; i < 4; i++)
#pragma unroll
            for (int j = 0; j < 4; j++) o[i][j] *= fr[i];

#pragma unroll 8
        for (int kk = 0; kk < 64; kk++) {
            float4 v = *reinterpret_cast<const float4*>(&Vs[kk * 64 + tx * 4]);
            float va[4] = {v.x, v.y, v.z, v.w};
            float p0 = Ss[(ty * 4 + 0) * SPT + kk];
            float p1 = Ss[(ty * 4 + 1) * SPT + kk];
            float p2 = Ss[(ty * 4 + 2) * SPT + kk];
            float p3 = Ss[(ty * 4 + 3) * SPT + kk];
#pragma unroll
            for (int j = 0; j < 4; j++) {
                o[0][j] = fmaf(p0, va[j], o[0][j]);
                o[1][j] = fmaf(p1, va[j], o[1][j]);
                o[2][j] = fmaf(p2, va[j], o[2][j]);
                o[3][j] = fmaf(p3, va[j], o[3][j]);
            }
        }
        __syncthreads();   // protect Ks/Vs/Ss before next iteration
    }

    // Normalize and write to g_attn in [B,S,H*DK] layout
    const int b = bh >> 4;
    const int h = bh & 15;
#pragma unroll
    for (int i = 0; i < 4; i++) {
        int r = ty * 4 + i;
        float inv = 1.0f / l_i[r];
        int s = q0 + r;
#pragma unroll
        for (int j = 0; j < 4; j++) {
            int d = tx * 4 + j;
            g_attn[((size_t)b * SEQ + s) * DMODEL + h * DK + d] = o[i][j] * inv;
        }
    }
}

// ---------------------------------------------------------------------------
extern "C" void kernel_launch(void* const* d_in, const int* in_sizes, int n_in,
                              void* d_out, int out_size)
{
    const float* x  = (const float*)d_in[0];
    const float* Wq = (const float*)d_in[1];
    const float* bq = (const float*)d_in[2];
    const float* Wk = (const float*)d_in[3];
    const float* bk = (const float*)d_in[4];
    const float* Wv = (const float*)d_in[5];
    const float* bv = (const float*)d_in[6];
    const float* Wo = (const float*)d_in[7];
    const float* bo = (const float*)d_in[8];
    float* out = (float*)d_out;

    (void)in_sizes; (void)n_in; (void)out_size;

    cudaFuncSetAttribute(attn_kernel, cudaFuncAttributeMaxDynamicSharedMemorySize,
                         (int)ATTN_SMEM);

    dim3 gQKV(MTOT / 128, DMODEL / 128, 3);
    qkv_kernel<<<gQKV, 256>>>(x, Wq, bq, Wk, bk, Wv, bv);

    dim3 gAttn(SEQ / 64, BATCH * NHEADS);
    attn_kernel<<<gAttn, 256, ATTN_SMEM>>>();

    dim3 gProj(MTOT / 128, DMODEL / 128);
    proj_kernel<<<gProj, 256>>>(Wo, bo, out);
}

// round 3
// speedup vs baseline: 1.3998x; 1.3998x over previous
#include <cuda_runtime.h>
#include <cuda_bf16.h>
#include <cstdint>
#include <math.h>

#define DMODEL 1024
#define NHEADS 16
#define DK     64
#define BATCH  4
#define SEQ    2048
#define MTOT   (BATCH*SEQ)   // 8192

// ---------------- device scratch (allocation-free) ----------------
__device__ float g_Q[(size_t)MTOT * DMODEL];     // [B,H,S,DK]
__device__ float g_K[(size_t)MTOT * DMODEL];
__device__ float g_V[(size_t)MTOT * DMODEL];
__device__ __nv_bfloat16 g_xh[(size_t)MTOT * DMODEL];
__device__ __nv_bfloat16 g_xl[(size_t)MTOT * DMODEL];
__device__ __nv_bfloat16 g_Wh[(size_t)4 * DMODEL * DMODEL];
__device__ __nv_bfloat16 g_Wl[(size_t)4 * DMODEL * DMODEL];
__device__ __nv_bfloat16 g_ah[(size_t)MTOT * DMODEL];   // attn out hi/lo [B,S,H*DK]
__device__ __nv_bfloat16 g_al[(size_t)MTOT * DMODEL];

// ---------------- helpers ----------------
__device__ __forceinline__ uint32_t smem_u32(const void* p) {
    uint32_t a;
    asm("{ .reg .u64 t; cvta.to.shared.u64 t, %1; cvt.u32.u64 %0, t; }" : "=r"(a) : "l"(p));
    return a;
}
__device__ __forceinline__ uint32_t swz(uint32_t o) { return o ^ ((o >> 3) & 0x70); }

__device__ __forceinline__ void cp16(uint32_t dst, const void* src) {
    asm volatile("cp.async.cg.shared.global [%0], [%1], 16;" :: "r"(dst), "l"(src));
}
#define CP_COMMIT() asm volatile("cp.async.commit_group;" ::: "memory")
#define CP_WAIT2()  asm volatile("cp.async.wait_group 2;" ::: "memory")

__device__ __forceinline__ void ldsm4(uint32_t* r, uint32_t a) {
    asm volatile("ldmatrix.sync.aligned.m8n8.x4.shared.b16 {%0,%1,%2,%3}, [%4];"
                 : "=r"(r[0]), "=r"(r[1]), "=r"(r[2]), "=r"(r[3]) : "r"(a));
}
__device__ __forceinline__ void mma16816(float* c, const uint32_t* a, const uint32_t* b) {
    asm volatile("mma.sync.aligned.m16n8k16.row.col.f32.bf16.bf16.f32 "
                 "{%0,%1,%2,%3}, {%4,%5,%6,%7}, {%8,%9}, {%0,%1,%2,%3};"
                 : "+f"(c[0]), "+f"(c[1]), "+f"(c[2]), "+f"(c[3])
                 : "r"(a[0]), "r"(a[1]), "r"(a[2]), "r"(a[3]), "r"(b[0]), "r"(b[1]));
}

// ---------------- hi/lo bf16 split ----------------
__global__ void split_kernel(const float4* __restrict__ src,
                             __nv_bfloat162* __restrict__ dh,
                             __nv_bfloat162* __restrict__ dl, int n4)
{
    int i = blockIdx.x * 256 + threadIdx.x;
    if (i < n4) {
        float4 v = src[i];
        __nv_bfloat16 h0 = __float2bfloat16(v.x);
        __nv_bfloat16 h1 = __float2bfloat16(v.y);
        __nv_bfloat16 h2 = __float2bfloat16(v.z);
        __nv_bfloat16 h3 = __float2bfloat16(v.w);
        __nv_bfloat16 l0 = __float2bfloat16(v.x - __bfloat162float(h0));
        __nv_bfloat16 l1 = __float2bfloat16(v.y - __bfloat162float(h1));
        __nv_bfloat16 l2 = __float2bfloat16(v.z - __bfloat162float(h2));
        __nv_bfloat16 l3 = __float2bfloat16(v.w - __bfloat162float(h3));
        dh[2 * i + 0] = __nv_bfloat162(h0, h1);
        dh[2 * i + 1] = __nv_bfloat162(h2, h3);
        dl[2 * i + 0] = __nv_bfloat162(l0, l1);
        dl[2 * i + 1] = __nv_bfloat162(l2, l3);
    }
}

// ---------------- mma.sync bf16 GEMM (3-term split folded into K'=3072) ----
// C[8192,1024] = A @ W^T + b.  CTA tile 128x128, k-chunk 64, 3-stage cp.async.
#define BM 128
#define BN 128
#define BK 64
#define NSTAGE 3
#define CHUNKS 48                       // 3 passes * (1024/64)
#define TILE_BYTES  (128 * 128)         // 128 rows x 128B
#define STAGE_BYTES (2 * TILE_BYTES)
#define GEMM_SMEM   (NSTAGE * STAGE_BYTES)

template <int MODE>  // 0 = QKV (blockIdx.z selects), 1 = output proj
__global__ __launch_bounds__(256, 1) void mma_gemm(
    const float* __restrict__ b0, const float* __restrict__ b1,
    const float* __restrict__ b2, float* __restrict__ outp)
{
    extern __shared__ char smg[];
    const uint32_t sbase = smem_u32(smg);
    const int tid = threadIdx.x, wid = tid >> 5, lane = tid & 31;
    const int warp_m = wid & 3, warp_n = wid >> 2;
    const int m0 = blockIdx.x * BM;
    const int n0 = blockIdx.y * BN;
    const int z  = (MODE == 0) ? blockIdx.z : 3;

    const __nv_bfloat16* Ah = (MODE == 0) ? g_xh : g_ah;
    const __nv_bfloat16* Al = (MODE == 0) ? g_xl : g_al;
    const __nv_bfloat16* Bh = g_Wh + (size_t)z * DMODEL * DMODEL;
    const __nv_bfloat16* Bl = g_Wl + (size_t)z * DMODEL * DMODEL;
    const float* bias = (MODE == 0) ? ((z == 0) ? b0 : ((z == 1) ? b1 : b2)) : b0;

    float cacc[2][8][4];
#pragma unroll
    for (int mi = 0; mi < 2; mi++)
#pragma unroll
        for (int ni = 0; ni < 8; ni++)
#pragma unroll
            for (int q = 0; q < 4; q++) cacc[mi][ni][q] = 0.f;

    auto load_chunk = [&](int c, int stage) {
        const int pass = c >> 4;
        const int kk = (c & 15) * BK;
        const __nv_bfloat16* As = (pass == 1) ? Al : Ah;
        const __nv_bfloat16* Bs = (pass == 2) ? Bl : Bh;
        const uint32_t sA = sbase + stage * STAGE_BYTES;
        const uint32_t sB = sA + TILE_BYTES;
#pragma unroll
        for (int i = 0; i < 4; i++) {
            int u = tid + i * 256;       // 0..1023
            int row = u >> 3, c16 = u & 7;
            cp16(sA + swz((uint32_t)(row * 128 + c16 * 16)),
                 As + (size_t)(m0 + row) * DMODEL + kk + c16 * 8);
            cp16(sB + swz((uint32_t)(row * 128 + c16 * 16)),
                 Bs + (size_t)(n0 + row) * DMODEL + kk + c16 * 8);
        }
    };

    load_chunk(0, 0); CP_COMMIT();
    load_chunk(1, 1); CP_COMMIT();

    for (int c = 0; c < CHUNKS; c++) {
        if (c + 2 < CHUNKS) load_chunk(c + 2, (c + 2) % NSTAGE);
        CP_COMMIT();
        CP_WAIT2();
        __syncthreads();

        const uint32_t sA = sbase + (c % NSTAGE) * STAGE_BYTES;
        const uint32_t sB = sA + TILE_BYTES;

#pragma unroll
        for (int ks = 0; ks < 4; ks++) {
            uint32_t a[2][4], b[4][4];
#pragma unroll
            for (int mi = 0; mi < 2; mi++) {
                int r = warp_m * 32 + mi * 16 + (lane & 15);
                ldsm4(a[mi], sA + swz((uint32_t)(r * 128 + ks * 32 + ((lane >> 4) << 4))));
            }
#pragma unroll
            for (int nb = 0; nb < 4; nb++) {
                int n = warp_n * 64 + nb * 16 + (lane & 7) + ((lane >> 4) << 3);
                ldsm4(b[nb], sB + swz((uint32_t)(n * 128 + ks * 32 + (((lane >> 3) & 1) << 4))));
            }
#pragma unroll
            for (int mi = 0; mi < 2; mi++)
#pragma unroll
                for (int ni = 0; ni < 8; ni++)
                    mma16816(cacc[mi][ni], a[mi], &b[ni >> 1][(ni & 1) * 2]);
        }
        __syncthreads();
    }

    // Epilogue
    const int row_base = m0 + warp_m * 32 + (lane >> 2);
    const int col_base = n0 + warp_n * 64 + (lane & 3) * 2;
#pragma unroll
    for (int ni = 0; ni < 8; ni++) {
        const int cc = col_base + ni * 8;
        const float bz0 = __ldg(&bias[cc]);
        const float bz1 = __ldg(&bias[cc + 1]);
#pragma unroll
        for (int mi = 0; mi < 2; mi++) {
#pragma unroll
            for (int half = 0; half < 2; half++) {
                const int m = row_base + mi * 16 + half * 8;
                float2 v;
                v.x = cacc[mi][ni][half * 2 + 0] + bz0;
                v.y = cacc[mi][ni][half * 2 + 1] + bz1;
                if (MODE == 0) {
                    const int bb = m >> 11, s = m & (SEQ - 1);
                    const int hd = cc >> 6, d = cc & 63;
                    float* out = (z == 0) ? g_Q : ((z == 1) ? g_K : g_V);
                    *reinterpret_cast<float2*>(
                        &out[(((size_t)(bb * NHEADS + hd)) * SEQ + s) * DK + d]) = v;
                } else {
                    *reinterpret_cast<float2*>(&outp[(size_t)m * DMODEL + cc]) = v;
                }
            }
        }
    }
}

// ---------------- Causal flash attention (fp32 SIMT) ----------------
#define SPT 65
#define ATTN_SMEM ((3*64*64 + 64*SPT + 3*64) * sizeof(float))

__global__ __launch_bounds__(256) void attn_kernel()
{
    extern __shared__ float sm[];
    float* Qs  = sm;
    float* Ks  = sm + 4096;
    float* Vs  = sm + 8192;
    float* Ss  = sm + 12288;
    float* m_i = sm + 12288 + 64 * SPT;
    float* l_i = m_i + 64;
    float* fac = l_i + 64;

    const int qt = blockIdx.x;
    const int bh = blockIdx.y;
    const int q0 = qt * 64;
    const size_t base = (size_t)bh * SEQ * DK;

    const int tid = threadIdx.x;
    const int tx  = tid & 15;
    const int ty  = tid >> 4;

    const float scale = 0.125f;
#pragma unroll
    for (int it = 0; it < 16; it++) {
        int e = tid + 256 * it;
        int r = e >> 6, d = e & 63;
        Qs[d * 64 + r] = g_Q[base + (size_t)(q0 + r) * DK + d] * scale;
    }
    if (tid < 64) { m_i[tid] = -3.0e38f; l_i[tid] = 0.f; }

    float o[4][4];
#pragma unroll
    for (int i = 0; i < 4; i++)
#pragma unroll
        for (int j = 0; j < 4; j++) o[i][j] = 0.f;

    __syncthreads();

    for (int kt = 0; kt <= qt; kt++) {
        const int k0 = kt * 64;
#pragma unroll
        for (int it = 0; it < 16; it++) {
            int e = tid + 256 * it;
            int c = e >> 6, d = e & 63;
            Ks[d * 64 + c] = g_K[base + (size_t)(k0 + c) * DK + d];
            Vs[e]          = g_V[base + (size_t)k0 * DK + e];
        }
        __syncthreads();

        float sacc[4][4];
#pragma unroll
        for (int i = 0; i < 4; i++)
#pragma unroll
            for (int j = 0; j < 4; j++) sacc[i][j] = 0.f;

#pragma unroll 8
        for (int d = 0; d < 64; d++) {
            float4 qv = *reinterpret_cast<const float4*>(&Qs[d * 64 + ty * 4]);
            float4 kv = *reinterpret_cast<const float4*>(&Ks[d * 64 + tx * 4]);
            float qa[4] = {qv.x, qv.y, qv.z, qv.w};
            float ka[4] = {kv.x, kv.y, kv.z, kv.w};
#pragma unroll
            for (int i = 0; i < 4; i++)
#pragma unroll
                for (int j = 0; j < 4; j++)
                    sacc[i][j] = fmaf(qa[i], ka[j], sacc[i][j]);
        }

        if (kt == qt) {
#pragma unroll
            for (int i = 0; i < 4; i++)
#pragma unroll
                for (int j = 0; j < 4; j++)
                    if (tx * 4 + j > ty * 4 + i) sacc[i][j] = -1.0e30f;
        }
#pragma unroll
        for (int i = 0; i < 4; i++)
#pragma unroll
            for (int j = 0; j < 4; j++)
                Ss[(ty * 4 + i) * SPT + tx * 4 + j] = sacc[i][j];
        __syncthreads();

        if (tid < 64) {
            float* row = &Ss[tid * SPT];
            float mx = m_i[tid];
#pragma unroll 8
            for (int c = 0; c < 64; c++) mx = fmaxf(mx, row[c]);
            float f = __expf(m_i[tid] - mx);
            float sum = 0.f;
#pragma unroll 8
            for (int c = 0; c < 64; c++) {
                float p = __expf(row[c] - mx);
                row[c] = p;
                sum += p;
            }
            l_i[tid] = l_i[tid] * f + sum;
            m_i[tid] = mx;
            fac[tid] = f;
        }
        __syncthreads();

        float fr[4];
#pragma unroll
        for (int i = 0; i < 4; i++) fr[i] = fac[ty * 4 + i];
#pragma unroll
        for (int i = 0; i < 4; i++)
#pragma unroll
            for (int j = 0; j < 4; j++) o[i][j] *= fr[i];

#pragma unroll 8
        for (int kk = 0; kk < 64; kk++) {
            float4 v = *reinterpret_cast<const float4*>(&Vs[kk * 64 + tx * 4]);
            float va[4] = {v.x, v.y, v.z, v.w};
            float p0 = Ss[(ty * 4 + 0) * SPT + kk];
            float p1 = Ss[(ty * 4 + 1) * SPT + kk];
            float p2 = Ss[(ty * 4 + 2) * SPT + kk];
            float p3 = Ss[(ty * 4 + 3) * SPT + kk];
#pragma unroll
            for (int j = 0; j < 4; j++) {
                o[0][j] = fmaf(p0, va[j], o[0][j]);
                o[1][j] = fmaf(p1, va[j], o[1][j]);
                o[2][j] = fmaf(p2, va[j], o[2][j]);
                o[3][j] = fmaf(p3, va[j], o[3][j]);
            }
        }
        __syncthreads();
    }

    // Normalize + bf16 hi/lo split to [B,S,H*DK]
    const int b  = bh >> 4;
    const int hd = bh & 15;
#pragma unroll
    for (int i = 0; i < 4; i++) {
        int r = ty * 4 + i;
        float inv = 1.0f / l_i[r];
        int s = q0 + r;
#pragma unroll
        for (int j = 0; j < 4; j++) {
            int d = tx * 4 + j;
            float val = o[i][j] * inv;
            __nv_bfloat16 h = __float2bfloat16(val);
            size_t idx = ((size_t)b * SEQ + s) * DMODEL + hd * DK + d;
            g_ah[idx] = h;
            g_al[idx] = __float2bfloat16(val - __bfloat162float(h));
        }
    }
}

// ---------------------------------------------------------------------------
extern "C" void kernel_launch(void* const* d_in, const int* in_sizes, int n_in,
                              void* d_out, int out_size)
{
    const float* x  = (const float*)d_in[0];
    const float* Wq = (const float*)d_in[1];
    const float* bq = (const float*)d_in[2];
    const float* Wk = (const float*)d_in[3];
    const float* bk = (const float*)d_in[4];
    const float* Wv = (const float*)d_in[5];
    const float* bv = (const float*)d_in[6];
    const float* Wo = (const float*)d_in[7];
    const float* bo = (const float*)d_in[8];
    float* out = (float*)d_out;
    (void)in_sizes; (void)n_in; (void)out_size;

    static bool attr_done = false;
    if (!attr_done) {
        cudaFuncSetAttribute(mma_gemm<0>, cudaFuncAttributeMaxDynamicSharedMemorySize, GEMM_SMEM);
        cudaFuncSetAttribute(mma_gemm<1>, cudaFuncAttributeMaxDynamicSharedMemorySize, GEMM_SMEM);
        cudaFuncSetAttribute(attn_kernel, cudaFuncAttributeMaxDynamicSharedMemorySize, (int)ATTN_SMEM);
        attr_done = true;
    }

    __nv_bfloat16 *xh, *xl, *Wh, *Wl;
    cudaGetSymbolAddress((void**)&xh, g_xh);
    cudaGetSymbolAddress((void**)&xl, g_xl);
    cudaGetSymbolAddress((void**)&Wh, g_Wh);
    cudaGetSymbolAddress((void**)&Wl, g_Wl);

    const int n4x = MTOT * DMODEL / 4;
    const int n4w = DMODEL * DMODEL / 4;
    split_kernel<<<(n4x + 255) / 256, 256>>>((const float4*)x,
        (__nv_bfloat162*)xh, (__nv_bfloat162*)xl, n4x);
    const float* Ws[4] = {Wq, Wk, Wv, Wo};
    for (int z = 0; z < 4; z++) {
        split_kernel<<<(n4w + 255) / 256, 256>>>((const float4*)Ws[z],
            (__nv_bfloat162*)(Wh + (size_t)z * DMODEL * DMODEL),
            (__nv_bfloat162*)(Wl + (size_t)z * DMODEL * DMODEL), n4w);
    }

    dim3 gQKV(MTOT / BM, DMODEL / BN, 3);
    mma_gemm<0><<<gQKV, 256, GEMM_SMEM>>>(bq, bk, bv, nullptr);

    dim3 gAttn(SEQ / 64, BATCH * NHEADS);
    attn_kernel<<<gAttn, 256, ATTN_SMEM>>>();

    dim3 gProj(MTOT / BM, DMODEL / BN);
    mma_gemm<1><<<gProj, 256, GEMM_SMEM>>>(bo, nullptr, nullptr, out);
}

// round 4
// speedup vs baseline: 3.1286x; 2.2349x over previous
#include <cuda_runtime.h>
#include <cuda_bf16.h>
#include <cstdint>
#include <math.h>

#define DMODEL 1024
#define NHEADS 16
#define DK     64
#define BATCH  4
#define SEQ    2048
#define MTOT   (BATCH*SEQ)   // 8192

#define QSCALE 0.1803368801111204f   // 0.125 * log2(e)

// ---------------- device scratch (allocation-free) ----------------
__device__ __nv_bfloat16 g_Qh[(size_t)MTOT * DMODEL];  // [B*H][S][DK]
__device__ __nv_bfloat16 g_Ql[(size_t)MTOT * DMODEL];
__device__ __nv_bfloat16 g_Kh[(size_t)MTOT * DMODEL];
__device__ __nv_bfloat16 g_Kl[(size_t)MTOT * DMODEL];
__device__ __nv_bfloat16 g_Vh[(size_t)MTOT * DMODEL];
__device__ __nv_bfloat16 g_Vl[(size_t)MTOT * DMODEL];
__device__ __nv_bfloat16 g_xh[(size_t)MTOT * DMODEL];
__device__ __nv_bfloat16 g_xl[(size_t)MTOT * DMODEL];
__device__ __nv_bfloat16 g_Wh[(size_t)4 * DMODEL * DMODEL];
__device__ __nv_bfloat16 g_Wl[(size_t)4 * DMODEL * DMODEL];
__device__ __nv_bfloat16 g_ah[(size_t)MTOT * DMODEL];   // attn out [B,S,H*DK]
__device__ __nv_bfloat16 g_al[(size_t)MTOT * DMODEL];

// ---------------- helpers ----------------
__device__ __forceinline__ uint32_t smem_u32(const void* p) {
    uint32_t a;
    asm("{ .reg .u64 t; cvta.to.shared.u64 t, %1; cvt.u32.u64 %0, t; }" : "=r"(a) : "l"(p));
    return a;
}
__device__ __forceinline__ uint32_t swz(uint32_t o) { return o ^ ((o >> 3) & 0x70); }

__device__ __forceinline__ void cp16(uint32_t dst, const void* src) {
    asm volatile("cp.async.cg.shared.global [%0], [%1], 16;" :: "r"(dst), "l"(src));
}
#define CP_COMMIT() asm volatile("cp.async.commit_group;" ::: "memory")
#define CP_WAIT1()  asm volatile("cp.async.wait_group 1;" ::: "memory")
#define CP_WAIT2()  asm volatile("cp.async.wait_group 2;" ::: "memory")

__device__ __forceinline__ void ldsm4(uint32_t* r, uint32_t a) {
    asm volatile("ldmatrix.sync.aligned.m8n8.x4.shared.b16 {%0,%1,%2,%3}, [%4];"
                 : "=r"(r[0]), "=r"(r[1]), "=r"(r[2]), "=r"(r[3]) : "r"(a));
}
__device__ __forceinline__ void ldsm4t(uint32_t* r, uint32_t a) {
    asm volatile("ldmatrix.sync.aligned.m8n8.x4.trans.shared.b16 {%0,%1,%2,%3}, [%4];"
                 : "=r"(r[0]), "=r"(r[1]), "=r"(r[2]), "=r"(r[3]) : "r"(a));
}
__device__ __forceinline__ void mma16816(float* c, const uint32_t* a, const uint32_t* b) {
    asm volatile("mma.sync.aligned.m16n8k16.row.col.f32.bf16.bf16.f32 "
                 "{%0,%1,%2,%3}, {%4,%5,%6,%7}, {%8,%9}, {%0,%1,%2,%3};"
                 : "+f"(c[0]), "+f"(c[1]), "+f"(c[2]), "+f"(c[3])
                 : "r"(a[0]), "r"(a[1]), "r"(a[2]), "r"(a[3]), "r"(b[0]), "r"(b[1]));
}

// Fast exp2 for t <= 0 (FMA pipe; err ~4e-5 rel)
__device__ __forceinline__ float exp2f_fast(float t) {
    t = fmaxf(t, -80.0f);
    float a = __fadd_rn(t, 12582912.0f);            // round-to-int via magic
    float r = __fsub_rn(t, __fsub_rn(a, 12582912.0f));
    float p = fmaf(r, 0.0096181291f, 0.0555041087f);
    p = fmaf(p, r, 0.2402265069f);
    p = fmaf(p, r, 0.6931471806f);
    p = fmaf(p, r, 1.0f);
    return __int_as_float(__float_as_int(p) + (__float_as_int(a) << 23));
}

__device__ __forceinline__ void split2(float x, float y, uint32_t& hi, uint32_t& lo) {
    __nv_bfloat16 hx = __float2bfloat16(x), hy = __float2bfloat16(y);
    __nv_bfloat162 h(hx, hy);
    hi = *reinterpret_cast<uint32_t*>(&h);
    __nv_bfloat162 l(__float2bfloat16(x - __bfloat162float(hx)),
                     __float2bfloat16(y - __bfloat162float(hy)));
    lo = *reinterpret_cast<uint32_t*>(&l);
}

__device__ __forceinline__ void store_hl(__nv_bfloat16* ah, __nv_bfloat16* al,
                                         size_t idx, float x, float y) {
    __nv_bfloat16 hx = __float2bfloat16(x), hy = __float2bfloat16(y);
    *reinterpret_cast<__nv_bfloat162*>(ah + idx) = __nv_bfloat162(hx, hy);
    *reinterpret_cast<__nv_bfloat162*>(al + idx) =
        __nv_bfloat162(__float2bfloat16(x - __bfloat162float(hx)),
                       __float2bfloat16(y - __bfloat162float(hy)));
}

// ---------------- hi/lo bf16 split ----------------
__global__ void split_kernel(const float4* __restrict__ src,
                             __nv_bfloat162* __restrict__ dh,
                             __nv_bfloat162* __restrict__ dl, int n4)
{
    int i = blockIdx.x * 256 + threadIdx.x;
    if (i < n4) {
        float4 v = src[i];
        uint32_t h0, l0, h1, l1;
        split2(v.x, v.y, h0, l0);
        split2(v.z, v.w, h1, l1);
        dh[2 * i + 0] = *reinterpret_cast<__nv_bfloat162*>(&h0);
        dh[2 * i + 1] = *reinterpret_cast<__nv_bfloat162*>(&h1);
        dl[2 * i + 0] = *reinterpret_cast<__nv_bfloat162*>(&l0);
        dl[2 * i + 1] = *reinterpret_cast<__nv_bfloat162*>(&l1);
    }
}

// ---------------- mma.sync bf16 GEMM (3-term split, K'=3072) ----------------
#define BM 128
#define BN 128
#define BK 64
#define NSTAGE 3
#define CHUNKS 48
#define TILE_BYTES  (128 * 128)
#define STAGE_BYTES (2 * TILE_BYTES)
#define GEMM_SMEM   (NSTAGE * STAGE_BYTES)

template <int MODE>  // 0 = QKV, 1 = output proj
__global__ __launch_bounds__(256, 1) void mma_gemm(
    const float* __restrict__ b0, const float* __restrict__ b1,
    const float* __restrict__ b2, float* __restrict__ outp)
{
    extern __shared__ char smg[];
    const uint32_t sbase = smem_u32(smg);
    const int tid = threadIdx.x, wid = tid >> 5, lane = tid & 31;
    const int warp_m = wid & 3, warp_n = wid >> 2;
    const int m0 = blockIdx.x * BM;
    const int n0 = blockIdx.y * BN;
    const int z  = (MODE == 0) ? blockIdx.z : 3;

    const __nv_bfloat16* Ah = (MODE == 0) ? g_xh : g_ah;
    const __nv_bfloat16* Al = (MODE == 0) ? g_xl : g_al;
    const __nv_bfloat16* Bh = g_Wh + (size_t)z * DMODEL * DMODEL;
    const __nv_bfloat16* Bl = g_Wl + (size_t)z * DMODEL * DMODEL;
    const float* bias = (MODE == 0) ? ((z == 0) ? b0 : ((z == 1) ? b1 : b2)) : b0;

    float cacc[2][8][4];
#pragma unroll
    for (int mi = 0; mi < 2; mi++)
#pragma unroll
        for (int ni = 0; ni < 8; ni++)
#pragma unroll
            for (int q = 0; q < 4; q++) cacc[mi][ni][q] = 0.f;

    auto load_chunk = [&](int c, int stage) {
        const int pass = c >> 4;
        const int kk = (c & 15) * BK;
        const __nv_bfloat16* As = (pass == 1) ? Al : Ah;
        const __nv_bfloat16* Bs = (pass == 2) ? Bl : Bh;
        const uint32_t sA = sbase + stage * STAGE_BYTES;
        const uint32_t sB = sA + TILE_BYTES;
#pragma unroll
        for (int i = 0; i < 4; i++) {
            int u = tid + i * 256;
            int row = u >> 3, c16 = u & 7;
            cp16(sA + swz((uint32_t)(row * 128 + c16 * 16)),
                 As + (size_t)(m0 + row) * DMODEL + kk + c16 * 8);
            cp16(sB + swz((uint32_t)(row * 128 + c16 * 16)),
                 Bs + (size_t)(n0 + row) * DMODEL + kk + c16 * 8);
        }
    };

    load_chunk(0, 0); CP_COMMIT();
    load_chunk(1, 1); CP_COMMIT();

    for (int c = 0; c < CHUNKS; c++) {
        if (c + 2 < CHUNKS) load_chunk(c + 2, (c + 2) % NSTAGE);
        CP_COMMIT();
        CP_WAIT2();
        __syncthreads();

        const uint32_t sA = sbase + (c % NSTAGE) * STAGE_BYTES;
        const uint32_t sB = sA + TILE_BYTES;

#pragma unroll
        for (int ks = 0; ks < 4; ks++) {
            uint32_t a[2][4], b[4][4];
#pragma unroll
            for (int mi = 0; mi < 2; mi++) {
                int r = warp_m * 32 + mi * 16 + (lane & 15);
                ldsm4(a[mi], sA + swz((uint32_t)(r * 128 + ks * 32 + ((lane >> 4) << 4))));
            }
#pragma unroll
            for (int nb = 0; nb < 4; nb++) {
                int n = warp_n * 64 + nb * 16 + (lane & 7) + ((lane >> 4) << 3);
                ldsm4(b[nb], sB + swz((uint32_t)(n * 128 + ks * 32 + (((lane >> 3) & 1) << 4))));
            }
#pragma unroll
            for (int mi = 0; mi < 2; mi++)
#pragma unroll
                for (int ni = 0; ni < 8; ni++)
                    mma16816(cacc[mi][ni], a[mi], &b[ni >> 1][(ni & 1) * 2]);
        }
        __syncthreads();
    }

    const int row_base = m0 + warp_m * 32 + (lane >> 2);
    const int col_base = n0 + warp_n * 64 + (lane & 3) * 2;
#pragma unroll
    for (int ni = 0; ni < 8; ni++) {
        const int cc = col_base + ni * 8;
        const float bz0 = __ldg(&bias[cc]);
        const float bz1 = __ldg(&bias[cc + 1]);
#pragma unroll
        for (int mi = 0; mi < 2; mi++) {
#pragma unroll
            for (int half = 0; half < 2; half++) {
                const int m = row_base + mi * 16 + half * 8;
                float vx = cacc[mi][ni][half * 2 + 0] + bz0;
                float vy = cacc[mi][ni][half * 2 + 1] + bz1;
                if (MODE == 0) {
                    const int bb = m >> 11, s = m & (SEQ - 1);
                    const int hd = cc >> 6, d = cc & 63;
                    if (z == 0) { vx *= QSCALE; vy *= QSCALE; }
                    __nv_bfloat16* dh = (z == 0) ? g_Qh : ((z == 1) ? g_Kh : g_Vh);
                    __nv_bfloat16* dl = (z == 0) ? g_Ql : ((z == 1) ? g_Kl : g_Vl);
                    size_t idx = (((size_t)(bb * NHEADS + hd)) * SEQ + s) * DK + d;
                    store_hl(dh, dl, idx, vx, vy);
                } else {
                    float2 v; v.x = vx; v.y = vy;
                    *reinterpret_cast<float2*>(&outp[(size_t)m * DMODEL + cc]) = v;
                }
            }
        }
    }
}

// ---------------- tensor-core causal flash attention ----------------
// Q tile 128, K tile 64. 8 warps, each warp = 16 q-rows x full 64 cols.
// smem: Qh(16K) Ql(16K) + 2 stages x (Kh,Kl,Vh,Vl @ 8K each = 32K) = 96KB
#define AQ_BYTES     32768
#define ASTAGE_BYTES 32768
#define ATTN_SMEM    (AQ_BYTES + 2 * ASTAGE_BYTES)

__global__ __launch_bounds__(256, 1) void attn_mma_kernel()
{
    extern __shared__ char smem[];
    const uint32_t sb = smem_u32(smem);
    const int tid = threadIdx.x, wid = tid >> 5, lane = tid & 31;
    const int qi = blockIdx.x, bh = blockIdx.y;
    const int q0 = qi * 128;
    const size_t base = (size_t)bh * SEQ * DK;

    const uint32_t sQh = sb;
    const uint32_t sQl = sb + 16384;

    // Q tiles: 2 x 1024 x16B / 256 threads
#pragma unroll
    for (int i = 0; i < 4; i++) {
        int u = tid + i * 256;
        int row = u >> 3, c16 = u & 7;
        cp16(sQh + swz((uint32_t)(row * 128 + c16 * 16)),
             g_Qh + base + (size_t)(q0 + row) * DK + c16 * 8);
        cp16(sQl + swz((uint32_t)(row * 128 + c16 * 16)),
             g_Ql + base + (size_t)(q0 + row) * DK + c16 * 8);
    }
    CP_COMMIT();

    const int nkt = 2 * qi + 2;
    auto load_kv = [&](int kt) {
        uint32_t st = sb + AQ_BYTES + (uint32_t)(kt & 1) * ASTAGE_BYTES;
        const size_t ko = base + (size_t)kt * 64 * DK;
        const __nv_bfloat16* srcs[4] = { g_Kh + ko, g_Kl + ko, g_Vh + ko, g_Vl + ko };
#pragma unroll
        for (int t4 = 0; t4 < 4; t4++) {
#pragma unroll
            for (int i = 0; i < 2; i++) {
                int u = tid * 2 + i;          // 0..511
                int row = u >> 3, c16 = u & 7;
                cp16(st + t4 * 8192 + swz((uint32_t)(row * 128 + c16 * 16)),
                     srcs[t4] + (size_t)row * DK + c16 * 8);
            }
        }
    };

    load_kv(0); CP_COMMIT();
    CP_WAIT1();               // Q ready
    __syncthreads();

    // Q fragments (loop-invariant)
    uint32_t qh[4][4], ql[4][4];
    {
        int r = wid * 16 + (lane & 15);
        uint32_t half = (uint32_t)((lane >> 4) << 4);
#pragma unroll
        for (int kc = 0; kc < 4; kc++) {
            ldsm4(qh[kc], sQh + swz((uint32_t)(r * 128 + kc * 32) + half));
            ldsm4(ql[kc], sQl + swz((uint32_t)(r * 128 + kc * 32) + half));
        }
    }

    float o[8][4];
#pragma unroll
    for (int nt = 0; nt < 8; nt++)
#pragma unroll
        for (int q = 0; q < 4; q++) o[nt][q] = 0.f;
    float m0v = -3.0e38f, m1v = -3.0e38f, l0 = 0.f, l1 = 0.f;

    const int rq = q0 + wid * 16 + (lane >> 2);

    for (int kt = 0; kt < nkt; kt++) {
        if (kt + 1 < nkt) load_kv(kt + 1);
        CP_COMMIT();
        CP_WAIT1();
        __syncthreads();

        const uint32_t st = sb + AQ_BYTES + (uint32_t)(kt & 1) * ASTAGE_BYTES;

        // ---- S = Q K^T (3-term) ----
        float s[8][4];
#pragma unroll
        for (int nt = 0; nt < 8; nt++)
#pragma unroll
            for (int q = 0; q < 4; q++) s[nt][q] = 0.f;

        const int nrow = (lane & 7) + ((lane >> 4) << 3);
        const uint32_t koff = (uint32_t)(((lane >> 3) & 1) << 4);
#pragma unroll
        for (int kc = 0; kc < 4; kc++) {
            uint32_t kb[16];
#pragma unroll
            for (int nb = 0; nb < 4; nb++)
                ldsm4(kb + nb * 4, st + swz((uint32_t)((nb * 16 + nrow) * 128 + kc * 32) + koff));
#pragma unroll
            for (int nt = 0; nt < 8; nt++) mma16816(s[nt], qh[kc], &kb[nt * 2]);
#pragma unroll
            for (int nt = 0; nt < 8; nt++) mma16816(s[nt], ql[kc], &kb[nt * 2]);
#pragma unroll
            for (int nb = 0; nb < 4; nb++)
                ldsm4(kb + nb * 4, st + 8192 + swz((uint32_t)((nb * 16 + nrow) * 128 + kc * 32) + koff));
#pragma unroll
            for (int nt = 0; nt < 8; nt++) mma16816(s[nt], qh[kc], &kb[nt * 2]);
        }

        // ---- causal mask (diagonal tiles only) ----
        if (kt * 64 + 63 > q0 + wid * 16) {
            const int cb = kt * 64 + 2 * (lane & 3);
#pragma unroll
            for (int nt = 0; nt < 8; nt++) {
                int c0 = cb + 8 * nt;
                if (c0     > rq)     s[nt][0] = -1.0e30f;
                if (c0 + 1 > rq)     s[nt][1] = -1.0e30f;
                if (c0     > rq + 8) s[nt][2] = -1.0e30f;
                if (c0 + 1 > rq + 8) s[nt][3] = -1.0e30f;
            }
        }

        // ---- online softmax (base-2, FMA-pipe exp) ----
        float mx0 = -3.0e38f, mx1 = -3.0e38f;
#pragma unroll
        for (int nt = 0; nt < 8; nt++) {
            mx0 = fmaxf(mx0, fmaxf(s[nt][0], s[nt][1]));
            mx1 = fmaxf(mx1, fmaxf(s[nt][2], s[nt][3]));
        }
        mx0 = fmaxf(mx0, __shfl_xor_sync(0xFFFFFFFFu, mx0, 1));
        mx0 = fmaxf(mx0, __shfl_xor_sync(0xFFFFFFFFu, mx0, 2));
        mx1 = fmaxf(mx1, __shfl_xor_sync(0xFFFFFFFFu, mx1, 1));
        mx1 = fmaxf(mx1, __shfl_xor_sync(0xFFFFFFFFu, mx1, 2));
        const float mn0 = fmaxf(m0v, mx0), mn1 = fmaxf(m1v, mx1);
        const float f0 = exp2f_fast(m0v - mn0), f1 = exp2f_fast(m1v - mn1);
        m0v = mn0; m1v = mn1;

        float sum0 = 0.f, sum1 = 0.f;
        uint32_t ph[4][4], pl[4][4];
#pragma unroll
        for (int kc = 0; kc < 4; kc++) {
            float e00 = exp2f_fast(s[2*kc][0]   - mn0);
            float e01 = exp2f_fast(s[2*kc][1]   - mn0);
            float e10 = exp2f_fast(s[2*kc][2]   - mn1);
            float e11 = exp2f_fast(s[2*kc][3]   - mn1);
            float e20 = exp2f_fast(s[2*kc+1][0] - mn0);
            float e21 = exp2f_fast(s[2*kc+1][1] - mn0);
            float e30 = exp2f_fast(s[2*kc+1][2] - mn1);
            float e31 = exp2f_fast(s[2*kc+1][3] - mn1);
            sum0 += (e00 + e01) + (e20 + e21);
            sum1 += (e10 + e11) + (e30 + e31);
            split2(e00, e01, ph[kc][0], pl[kc][0]);
            split2(e10, e11, ph[kc][1], pl[kc][1]);
            split2(e20, e21, ph[kc][2], pl[kc][2]);
            split2(e30, e31, ph[kc][3], pl[kc][3]);
        }
        sum0 += __shfl_xor_sync(0xFFFFFFFFu, sum0, 1);
        sum0 += __shfl_xor_sync(0xFFFFFFFFu, sum0, 2);
        sum1 += __shfl_xor_sync(0xFFFFFFFFu, sum1, 1);
        sum1 += __shfl_xor_sync(0xFFFFFFFFu, sum1, 2);
        l0 = l0 * f0 + sum0;
        l1 = l1 * f1 + sum1;

#pragma unroll
        for (int nt = 0; nt < 8; nt++) {
            o[nt][0] *= f0; o[nt][1] *= f0;
            o[nt][2] *= f1; o[nt][3] *= f1;
        }

        // ---- O += P V (3-term) ----
        const int vkey = ((lane >> 3) & 1) * 8 + (lane & 7);
        const uint32_t vdk = (uint32_t)(((lane >> 4) << 3) * 2);
#pragma unroll
        for (int kc = 0; kc < 4; kc++) {
            uint32_t vb[16];
#pragma unroll
            for (int p4 = 0; p4 < 4; p4++)
                ldsm4t(vb + p4 * 4, st + 16384 +
                       swz((uint32_t)((kc * 16 + vkey) * 128 + p4 * 32) + vdk));
#pragma unroll
            for (int nt = 0; nt < 8; nt++) mma16816(o[nt], ph[kc], &vb[nt * 2]);
#pragma unroll
            for (int nt = 0; nt < 8; nt++) mma16816(o[nt], pl[kc], &vb[nt * 2]);
#pragma unroll
            for (int p4 = 0; p4 < 4; p4++)
                ldsm4t(vb + p4 * 4, st + 24576 +
                       swz((uint32_t)((kc * 16 + vkey) * 128 + p4 * 32) + vdk));
#pragma unroll
            for (int nt = 0; nt < 8; nt++) mma16816(o[nt], ph[kc], &vb[nt * 2]);
        }
        __syncthreads();   // stage reusable
    }

    // ---- epilogue: normalize, split hi/lo, store [B,S,H*DK] ----
    const float inv0 = 1.0f / l0, inv1 = 1.0f / l1;
    const int b = bh >> 4, hd = bh & 15;
    const int dkb = 2 * (lane & 3);
#pragma unroll
    for (int nt = 0; nt < 8; nt++) {
        const int d = hd * 64 + dkb + 8 * nt;
        size_t i0 = ((size_t)b * SEQ + rq) * DMODEL + d;
        size_t i1 = ((size_t)b * SEQ + rq + 8) * DMODEL + d;
        store_hl(g_ah, g_al, i0, o[nt][0] * inv0, o[nt][1] * inv0);
        store_hl(g_ah, g_al, i1, o[nt][2] * inv1, o[nt][3] * inv1);
    }
}

// ---------------------------------------------------------------------------
extern "C" void kernel_launch(void* const* d_in, const int* in_sizes, int n_in,
                              void* d_out, int out_size)
{
    const float* x  = (const float*)d_in[0];
    const float* Wq = (const float*)d_in[1];
    const float* bq = (const float*)d_in[2];
    const float* Wk = (const float*)d_in[3];
    const float* bk = (const float*)d_in[4];
    const float* Wv = (const float*)d_in[5];
    const float* bv = (const float*)d_in[6];
    const float* Wo = (const float*)d_in[7];
    const float* bo = (const float*)d_in[8];
    float* out = (float*)d_out;
    (void)in_sizes; (void)n_in; (void)out_size;

    static bool attr_done = false;
    if (!attr_done) {
        cudaFuncSetAttribute(mma_gemm<0>, cudaFuncAttributeMaxDynamicSharedMemorySize, GEMM_SMEM);
        cudaFuncSetAttribute(mma_gemm<1>, cudaFuncAttributeMaxDynamicSharedMemorySize, GEMM_SMEM);
        cudaFuncSetAttribute(attn_mma_kernel, cudaFuncAttributeMaxDynamicSharedMemorySize, ATTN_SMEM);
        attr_done = true;
    }

    __nv_bfloat16 *xh, *xl, *Wh, *Wl;
    cudaGetSymbolAddress((void**)&xh, g_xh);
    cudaGetSymbolAddress((void**)&xl, g_xl);
    cudaGetSymbolAddress((void**)&Wh, g_Wh);
    cudaGetSymbolAddress((void**)&Wl, g_Wl);

    const int n4x = MTOT * DMODEL / 4;
    const int n4w = DMODEL * DMODEL / 4;
    split_kernel<<<(n4x + 255) / 256, 256>>>((const float4*)x,
        (__nv_bfloat162*)xh, (__nv_bfloat162*)xl, n4x);
    const float* Ws[4] = {Wq, Wk, Wv, Wo};
    for (int z = 0; z < 4; z++) {
        split_kernel<<<(n4w + 255) / 256, 256>>>((const float4*)Ws[z],
            (__nv_bfloat162*)(Wh + (size_t)z * DMODEL * DMODEL),
            (__nv_bfloat162*)(Wl + (size_t)z * DMODEL * DMODEL), n4w);
    }

    dim3 gQKV(MTOT / BM, DMODEL / BN, 3);
    mma_gemm<0><<<gQKV, 256, GEMM_SMEM>>>(bq, bk, bv, nullptr);

    dim3 gAttn(SEQ / 128, BATCH * NHEADS);
    attn_mma_kernel<<<gAttn, 256, ATTN_SMEM>>>();

    dim3 gProj(MTOT / BM, DMODEL / BN);
    mma_gemm<1><<<gProj, 256, GEMM_SMEM>>>(bo, nullptr, nullptr, out);
}

// round 5
// speedup vs baseline: 5.0216x; 1.6051x over previous
#include <cuda_runtime.h>
#include <cuda_fp16.h>
#include <cstdint>
#include <math.h>

#define DMODEL 1024
#define NHEADS 16
#define DK     64
#define BATCH  4
#define SEQ    2048
#define MTOT   (BATCH*SEQ)   // 8192

#define QSCALE 0.1803368801111204f   // 0.125 * log2(e)

// ---------------- device scratch (allocation-free) ----------------
__device__ __half g_Qh[(size_t)MTOT * DMODEL];  // [B*H][S][DK]
__device__ __half g_Ql[(size_t)MTOT * DMODEL];
__device__ __half g_Kh[(size_t)MTOT * DMODEL];  // hi only
__device__ __half g_Vh[(size_t)MTOT * DMODEL];  // hi only
__device__ __half g_xh[(size_t)MTOT * DMODEL];
__device__ __half g_xl[(size_t)MTOT * DMODEL];
__device__ __half g_Wh[(size_t)4 * DMODEL * DMODEL];   // weights hi only
__device__ __half g_ah[(size_t)MTOT * DMODEL];  // attn out hi/lo [B,S,H*DK]
__device__ __half g_al[(size_t)MTOT * DMODEL];

// ---------------- helpers ----------------
__device__ __forceinline__ uint32_t smem_u32(const void* p) {
    uint32_t a;
    asm("{ .reg .u64 t; cvta.to.shared.u64 t, %1; cvt.u32.u64 %0, t; }" : "=r"(a) : "l"(p));
    return a;
}
__device__ __forceinline__ uint32_t swz(uint32_t o) { return o ^ ((o >> 3) & 0x70); }

__device__ __forceinline__ void cp16(uint32_t dst, const void* src) {
    asm volatile("cp.async.cg.shared.global [%0], [%1], 16;" :: "r"(dst), "l"(src));
}
#define CP_COMMIT() asm volatile("cp.async.commit_group;" ::: "memory")
#define CP_WAIT0()  asm volatile("cp.async.wait_group 0;" ::: "memory")
#define CP_WAIT1()  asm volatile("cp.async.wait_group 1;" ::: "memory")

__device__ __forceinline__ void ldsm4(uint32_t* r, uint32_t a) {
    asm volatile("ldmatrix.sync.aligned.m8n8.x4.shared.b16 {%0,%1,%2,%3}, [%4];"
                 : "=r"(r[0]), "=r"(r[1]), "=r"(r[2]), "=r"(r[3]) : "r"(a));
}
__device__ __forceinline__ void ldsm4t(uint32_t* r, uint32_t a) {
    asm volatile("ldmatrix.sync.aligned.m8n8.x4.trans.shared.b16 {%0,%1,%2,%3}, [%4];"
                 : "=r"(r[0]), "=r"(r[1]), "=r"(r[2]), "=r"(r[3]) : "r"(a));
}
__device__ __forceinline__ void mma16816(float* c, const uint32_t* a, const uint32_t* b) {
    asm volatile("mma.sync.aligned.m16n8k16.row.col.f32.f16.f16.f32 "
                 "{%0,%1,%2,%3}, {%4,%5,%6,%7}, {%8,%9}, {%0,%1,%2,%3};"
                 : "+f"(c[0]), "+f"(c[1]), "+f"(c[2]), "+f"(c[3])
                 : "r"(a[0]), "r"(a[1]), "r"(a[2]), "r"(a[3]), "r"(b[0]), "r"(b[1]));
}

// Fast exp2 for t <= 0 (FMA pipe; err ~4e-5 rel)
__device__ __forceinline__ float exp2f_fast(float t) {
    t = fmaxf(t, -80.0f);
    float a = __fadd_rn(t, 12582912.0f);
    float r = __fsub_rn(t, __fsub_rn(a, 12582912.0f));
    float p = fmaf(r, 0.0096181291f, 0.0555041087f);
    p = fmaf(p, r, 0.2402265069f);
    p = fmaf(p, r, 0.6931471806f);
    p = fmaf(p, r, 1.0f);
    return __int_as_float(__float_as_int(p) + (__float_as_int(a) << 23));
}

__device__ __forceinline__ void split2(float x, float y, uint32_t& hi, uint32_t& lo) {
    __half hx = __float2half_rn(x), hy = __float2half_rn(y);
    __half2 h(hx, hy);
    hi = *reinterpret_cast<uint32_t*>(&h);
    __half2 l(__float2half_rn(x - __half2float(hx)),
              __float2half_rn(y - __half2float(hy)));
    lo = *reinterpret_cast<uint32_t*>(&l);
}
__device__ __forceinline__ void store_hl(__half* ah, __half* al,
                                         size_t idx, float x, float y) {
    __half hx = __float2half_rn(x), hy = __float2half_rn(y);
    *reinterpret_cast<__half2*>(ah + idx) = __half2(hx, hy);
    *reinterpret_cast<__half2*>(al + idx) =
        __half2(__float2half_rn(x - __half2float(hx)),
                __float2half_rn(y - __half2float(hy)));
}

// ---------------- splits ----------------
__global__ void split_kernel(const float4* __restrict__ src,
                             __half2* __restrict__ dh, __half2* __restrict__ dl, int n4)
{
    int i = blockIdx.x * 256 + threadIdx.x;
    if (i < n4) {
        float4 v = src[i];
        uint32_t h0, l0, h1, l1;
        split2(v.x, v.y, h0, l0);
        split2(v.z, v.w, h1, l1);
        dh[2 * i + 0] = *reinterpret_cast<__half2*>(&h0);
        dh[2 * i + 1] = *reinterpret_cast<__half2*>(&h1);
        dl[2 * i + 0] = *reinterpret_cast<__half2*>(&l0);
        dl[2 * i + 1] = *reinterpret_cast<__half2*>(&l1);
    }
}
__global__ void splitH_kernel(const float4* __restrict__ src,
                              __half2* __restrict__ dh, int n4)
{
    int i = blockIdx.x * 256 + threadIdx.x;
    if (i < n4) {
        float4 v = src[i];
        dh[2 * i + 0] = __half2(__float2half_rn(v.x), __float2half_rn(v.y));
        dh[2 * i + 1] = __half2(__float2half_rn(v.z), __float2half_rn(v.w));
    }
}

// ---------------- fp16 mma GEMM: C = A @ W^T + b, 2-term (Ah+Al)·Bh ----------
// CTA 128x128, chunk = 64 k, per-chunk tiles: Ah, Al, Bh (16KB each), 2 stages.
#define BM 128
#define BN 128
#define CHUNKS 16
#define ATILE 16384
#define STAGE_BYTES (3 * ATILE)
#define GEMM_SMEM   (2 * STAGE_BYTES)   // 96KB

template <int MODE>  // 0 = QKV, 1 = output proj
__global__ __launch_bounds__(256, 1) void mma_gemm(
    const float* __restrict__ b0, const float* __restrict__ b1,
    const float* __restrict__ b2, float* __restrict__ outp)
{
    extern __shared__ char smg[];
    const uint32_t sbase = smem_u32(smg);
    const int tid = threadIdx.x, wid = tid >> 5, lane = tid & 31;
    const int warp_m = wid & 3, warp_n = wid >> 2;
    const int m0 = blockIdx.x * BM;
    const int n0 = blockIdx.y * BN;
    const int z  = (MODE == 0) ? blockIdx.z : 3;

    const __half* Ah = (MODE == 0) ? g_xh : g_ah;
    const __half* Al = (MODE == 0) ? g_xl : g_al;
    const __half* Bh = g_Wh + (size_t)z * DMODEL * DMODEL;
    const float* bias = (MODE == 0) ? ((z == 0) ? b0 : ((z == 1) ? b1 : b2)) : b0;

    float cacc[2][8][4];
#pragma unroll
    for (int mi = 0; mi < 2; mi++)
#pragma unroll
        for (int ni = 0; ni < 8; ni++)
#pragma unroll
            for (int q = 0; q < 4; q++) cacc[mi][ni][q] = 0.f;

    auto load_chunk = [&](int c, int stage) {
        const int kk = c * 64;
        const uint32_t sAh = sbase + stage * STAGE_BYTES;
        const uint32_t sAl = sAh + ATILE;
        const uint32_t sB  = sAh + 2 * ATILE;
#pragma unroll
        for (int i = 0; i < 4; i++) {
            int u = tid + i * 256;       // 0..1023
            int row = u >> 3, c16 = u & 7;
            uint32_t so = swz((uint32_t)(row * 128 + c16 * 16));
            size_t go = (size_t)row * DMODEL + kk + c16 * 8;
            cp16(sAh + so, Ah + (size_t)m0 * DMODEL + go);
            cp16(sAl + so, Al + (size_t)m0 * DMODEL + go);
            cp16(sB  + so, Bh + (size_t)n0 * DMODEL + go);
        }
    };

    load_chunk(0, 0); CP_COMMIT();

    for (int c = 0; c < CHUNKS; c++) {
        if (c + 1 < CHUNKS) { load_chunk(c + 1, (c + 1) & 1); CP_COMMIT(); CP_WAIT1(); }
        else                { CP_WAIT0(); }
        __syncthreads();

        const uint32_t sAh = sbase + (c & 1) * STAGE_BYTES;
        const uint32_t sAl = sAh + ATILE;
        const uint32_t sB  = sAh + 2 * ATILE;

#pragma unroll
        for (int ks = 0; ks < 4; ks++) {
            uint32_t ah[2][4], al[2][4], b[4][4];
#pragma unroll
            for (int mi = 0; mi < 2; mi++) {
                int r = warp_m * 32 + mi * 16 + (lane & 15);
                uint32_t so = swz((uint32_t)(r * 128 + ks * 32 + ((lane >> 4) << 4)));
                ldsm4(ah[mi], sAh + so);
                ldsm4(al[mi], sAl + so);
            }
#pragma unroll
            for (int nb = 0; nb < 4; nb++) {
                int n = warp_n * 64 + nb * 16 + (lane & 7) + ((lane >> 4) << 3);
                ldsm4(b[nb], sB + swz((uint32_t)(n * 128 + ks * 32 + (((lane >> 3) & 1) << 4))));
            }
#pragma unroll
            for (int mi = 0; mi < 2; mi++)
#pragma unroll
                for (int ni = 0; ni < 8; ni++) {
                    mma16816(cacc[mi][ni], ah[mi], &b[ni >> 1][(ni & 1) * 2]);
                    mma16816(cacc[mi][ni], al[mi], &b[ni >> 1][(ni & 1) * 2]);
                }
        }
        __syncthreads();
    }

    const int row_base = m0 + warp_m * 32 + (lane >> 2);
    const int col_base = n0 + warp_n * 64 + (lane & 3) * 2;
#pragma unroll
    for (int ni = 0; ni < 8; ni++) {
        const int cc = col_base + ni * 8;
        const float bz0 = __ldg(&bias[cc]);
        const float bz1 = __ldg(&bias[cc + 1]);
#pragma unroll
        for (int mi = 0; mi < 2; mi++) {
#pragma unroll
            for (int half = 0; half < 2; half++) {
                const int m = row_base + mi * 16 + half * 8;
                float vx = cacc[mi][ni][half * 2 + 0] + bz0;
                float vy = cacc[mi][ni][half * 2 + 1] + bz1;
                if (MODE == 0) {
                    const int bb = m >> 11, s = m & (SEQ - 1);
                    const int hd = cc >> 6, d = cc & 63;
                    size_t idx = (((size_t)(bb * NHEADS + hd)) * SEQ + s) * DK + d;
                    if (z == 0) {
                        vx *= QSCALE; vy *= QSCALE;
                        store_hl(g_Qh, g_Ql, idx, vx, vy);
                    } else if (z == 1) {
                        *reinterpret_cast<__half2*>(g_Kh + idx) =
                            __half2(__float2half_rn(vx), __float2half_rn(vy));
                    } else {
                        *reinterpret_cast<__half2*>(g_Vh + idx) =
                            __half2(__float2half_rn(vx), __float2half_rn(vy));
                    }
                } else {
                    float2 v; v.x = vx; v.y = vy;
                    *reinterpret_cast<float2*>(&outp[(size_t)m * DMODEL + cc]) = v;
                }
            }
        }
    }
}

// ---------------- tensor-core causal flash attention (fp16, 2-term) --------
// Q tile 128 (Qh+Ql, 32KB), KV tile 64 (Kh 8K + Vh 8K), 2 stages = 32KB.
#define AQ_BYTES     32768
#define ASTAGE_BYTES 16384
#define ATTN_SMEM    (AQ_BYTES + 2 * ASTAGE_BYTES)   // 64KB

__global__ __launch_bounds__(256, 1) void attn_mma_kernel()
{
    extern __shared__ char smem[];
    const uint32_t sb = smem_u32(smem);
    const int tid = threadIdx.x, wid = tid >> 5, lane = tid & 31;
    const int qi = gridDim.x - 1 - blockIdx.x;   // long tiles first
    const int bh = blockIdx.y;
    const int q0 = qi * 128;
    const size_t base = (size_t)bh * SEQ * DK;

    const uint32_t sQh = sb;
    const uint32_t sQl = sb + 16384;

#pragma unroll
    for (int i = 0; i < 4; i++) {
        int u = tid + i * 256;
        int row = u >> 3, c16 = u & 7;
        uint32_t so = swz((uint32_t)(row * 128 + c16 * 16));
        cp16(sQh + so, g_Qh + base + (size_t)(q0 + row) * DK + c16 * 8);
        cp16(sQl + so, g_Ql + base + (size_t)(q0 + row) * DK + c16 * 8);
    }
    CP_COMMIT();

    const int nkt = 2 * qi + 2;
    auto load_kv = [&](int kt) {
        uint32_t st = sb + AQ_BYTES + (uint32_t)(kt & 1) * ASTAGE_BYTES;
        const size_t ko = base + (size_t)kt * 64 * DK;
#pragma unroll
        for (int i = 0; i < 2; i++) {
            int u = tid * 2 + i;          // 0..511
            int row = u >> 3, c16 = u & 7;
            uint32_t so = swz((uint32_t)(row * 128 + c16 * 16));
            cp16(st + so,        g_Kh + ko + (size_t)row * DK + c16 * 8);
            cp16(st + 8192 + so, g_Vh + ko + (size_t)row * DK + c16 * 8);
        }
    };

    load_kv(0); CP_COMMIT();
    CP_WAIT1();               // Q ready
    __syncthreads();

    uint32_t qh[4][4], ql[4][4];
    {
        int r = wid * 16 + (lane & 15);
        uint32_t half = (uint32_t)((lane >> 4) << 4);
#pragma unroll
        for (int kc = 0; kc < 4; kc++) {
            ldsm4(qh[kc], sQh + swz((uint32_t)(r * 128 + kc * 32) + half));
            ldsm4(ql[kc], sQl + swz((uint32_t)(r * 128 + kc * 32) + half));
        }
    }

    float o[8][4];
#pragma unroll
    for (int nt = 0; nt < 8; nt++)
#pragma unroll
        for (int q = 0; q < 4; q++) o[nt][q] = 0.f;
    float m0v = -3.0e38f, m1v = -3.0e38f, l0 = 0.f, l1 = 0.f;

    const int rq = q0 + wid * 16 + (lane >> 2);

    for (int kt = 0; kt < nkt; kt++) {
        if (kt + 1 < nkt) { load_kv(kt + 1); CP_COMMIT(); CP_WAIT1(); }
        else              { CP_WAIT0(); }
        __syncthreads();

        const uint32_t st = sb + AQ_BYTES + (uint32_t)(kt & 1) * ASTAGE_BYTES;

        // ---- S = Q K^T (Qh+Ql)·Kh ----
        float s[8][4];
#pragma unroll
        for (int nt = 0; nt < 8; nt++)
#pragma unroll
            for (int q = 0; q < 4; q++) s[nt][q] = 0.f;

        const int nrow = (lane & 7) + ((lane >> 4) << 3);
        const uint32_t koff = (uint32_t)(((lane >> 3) & 1) << 4);
#pragma unroll
        for (int kc = 0; kc < 4; kc++) {
            uint32_t kb[16];
#pragma unroll
            for (int nb = 0; nb < 4; nb++)
                ldsm4(kb + nb * 4, st + swz((uint32_t)((nb * 16 + nrow) * 128 + kc * 32) + koff));
#pragma unroll
            for (int nt = 0; nt < 8; nt++) mma16816(s[nt], qh[kc], &kb[nt * 2]);
#pragma unroll
            for (int nt = 0; nt < 8; nt++) mma16816(s[nt], ql[kc], &kb[nt * 2]);
        }

        // ---- causal mask ----
        if (kt * 64 + 63 > q0 + wid * 16) {
            const int cb = kt * 64 + 2 * (lane & 3);
#pragma unroll
            for (int nt = 0; nt < 8; nt++) {
                int c0 = cb + 8 * nt;
                if (c0     > rq)     s[nt][0] = -1.0e30f;
                if (c0 + 1 > rq)     s[nt][1] = -1.0e30f;
                if (c0     > rq + 8) s[nt][2] = -1.0e30f;
                if (c0 + 1 > rq + 8) s[nt][3] = -1.0e30f;
            }
        }

        // ---- online softmax ----
        float mx0 = -3.0e38f, mx1 = -3.0e38f;
#pragma unroll
        for (int nt = 0; nt < 8; nt++) {
            mx0 = fmaxf(mx0, fmaxf(s[nt][0], s[nt][1]));
            mx1 = fmaxf(mx1, fmaxf(s[nt][2], s[nt][3]));
        }
        mx0 = fmaxf(mx0, __shfl_xor_sync(0xFFFFFFFFu, mx0, 1));
        mx0 = fmaxf(mx0, __shfl_xor_sync(0xFFFFFFFFu, mx0, 2));
        mx1 = fmaxf(mx1, __shfl_xor_sync(0xFFFFFFFFu, mx1, 1));
        mx1 = fmaxf(mx1, __shfl_xor_sync(0xFFFFFFFFu, mx1, 2));
        const float mn0 = fmaxf(m0v, mx0), mn1 = fmaxf(m1v, mx1);
        const float f0 = exp2f_fast(m0v - mn0), f1 = exp2f_fast(m1v - mn1);
        m0v = mn0; m1v = mn1;

        float sum0 = 0.f, sum1 = 0.f;
        uint32_t ph[4][4], pl[4][4];
#pragma unroll
        for (int kc = 0; kc < 4; kc++) {
            float e00 = exp2f_fast(s[2*kc][0]   - mn0);
            float e01 = exp2f_fast(s[2*kc][1]   - mn0);
            float e10 = exp2f_fast(s[2*kc][2]   - mn1);
            float e11 = exp2f_fast(s[2*kc][3]   - mn1);
            float e20 = exp2f_fast(s[2*kc+1][0] - mn0);
            float e21 = exp2f_fast(s[2*kc+1][1] - mn0);
            float e30 = exp2f_fast(s[2*kc+1][2] - mn1);
            float e31 = exp2f_fast(s[2*kc+1][3] - mn1);
            sum0 += (e00 + e01) + (e20 + e21);
            sum1 += (e10 + e11) + (e30 + e31);
            split2(e00, e01, ph[kc][0], pl[kc][0]);
            split2(e10, e11, ph[kc][1], pl[kc][1]);
            split2(e20, e21, ph[kc][2], pl[kc][2]);
            split2(e30, e31, ph[kc][3], pl[kc][3]);
        }
        sum0 += __shfl_xor_sync(0xFFFFFFFFu, sum0, 1);
        sum0 += __shfl_xor_sync(0xFFFFFFFFu, sum0, 2);
        sum1 += __shfl_xor_sync(0xFFFFFFFFu, sum1, 1);
        sum1 += __shfl_xor_sync(0xFFFFFFFFu, sum1, 2);
        l0 = l0 * f0 + sum0;
        l1 = l1 * f1 + sum1;

#pragma unroll
        for (int nt = 0; nt < 8; nt++) {
            o[nt][0] *= f0; o[nt][1] *= f0;
            o[nt][2] *= f1; o[nt][3] *= f1;
        }

        // ---- O += (Ph+Pl)·Vh ----
        const int vkey = ((lane >> 3) & 1) * 8 + (lane & 7);
        const uint32_t vdk = (uint32_t)(((lane >> 4) << 3) * 2);
#pragma unroll
        for (int kc = 0; kc < 4; kc++) {
            uint32_t vb[16];
#pragma unroll
            for (int p4 = 0; p4 < 4; p4++)
                ldsm4t(vb + p4 * 4, st + 8192 +
                       swz((uint32_t)((kc * 16 + vkey) * 128 + p4 * 32) + vdk));
#pragma unroll
            for (int nt = 0; nt < 8; nt++) mma16816(o[nt], ph[kc], &vb[nt * 2]);
#pragma unroll
            for (int nt = 0; nt < 8; nt++) mma16816(o[nt], pl[kc], &vb[nt * 2]);
        }
        __syncthreads();
    }

    // ---- epilogue ----
    const float inv0 = 1.0f / l0, inv1 = 1.0f / l1;
    const int b = bh >> 4, hd = bh & 15;
    const int dkb = 2 * (lane & 3);
#pragma unroll
    for (int nt = 0; nt < 8; nt++) {
        const int d = hd * 64 + dkb + 8 * nt;
        size_t i0 = ((size_t)b * SEQ + rq) * DMODEL + d;
        size_t i1 = ((size_t)b * SEQ + rq + 8) * DMODEL + d;
        store_hl(g_ah, g_al, i0, o[nt][0] * inv0, o[nt][1] * inv0);
        store_hl(g_ah, g_al, i1, o[nt][2] * inv1, o[nt][3] * inv1);
    }
}

// ---------------------------------------------------------------------------
extern "C" void kernel_launch(void* const* d_in, const int* in_sizes, int n_in,
                              void* d_out, int out_size)
{
    const float* x  = (const float*)d_in[0];
    const float* Wq = (const float*)d_in[1];
    const float* bq = (const float*)d_in[2];
    const float* Wk = (const float*)d_in[3];
    const float* bk = (const float*)d_in[4];
    const float* Wv = (const float*)d_in[5];
    const float* bv = (const float*)d_in[6];
    const float* Wo = (const float*)d_in[7];
    const float* bo = (const float*)d_in[8];
    float* out = (float*)d_out;
    (void)in_sizes; (void)n_in; (void)out_size;

    static bool attr_done = false;
    if (!attr_done) {
        cudaFuncSetAttribute(mma_gemm<0>, cudaFuncAttributeMaxDynamicSharedMemorySize, GEMM_SMEM);
        cudaFuncSetAttribute(mma_gemm<1>, cudaFuncAttributeMaxDynamicSharedMemorySize, GEMM_SMEM);
        cudaFuncSetAttribute(attn_mma_kernel, cudaFuncAttributeMaxDynamicSharedMemorySize, ATTN_SMEM);
        attr_done = true;
    }

    __half *xh, *xl, *Wh;
    cudaGetSymbolAddress((void**)&xh, g_xh);
    cudaGetSymbolAddress((void**)&xl, g_xl);
    cudaGetSymbolAddress((void**)&Wh, g_Wh);

    const int n4x = MTOT * DMODEL / 4;
    const int n4w = DMODEL * DMODEL / 4;
    split_kernel<<<(n4x + 255) / 256, 256>>>((const float4*)x,
        (__half2*)xh, (__half2*)xl, n4x);
    const float* Ws[4] = {Wq, Wk, Wv, Wo};
    for (int z = 0; z < 4; z++) {
        splitH_kernel<<<(n4w + 255) / 256, 256>>>((const float4*)Ws[z],
            (__half2*)(Wh + (size_t)z * DMODEL * DMODEL), n4w);
    }

    dim3 gQKV(MTOT / BM, DMODEL / BN, 3);
    mma_gemm<0><<<gQKV, 256, GEMM_SMEM>>>(bq, bk, bv, nullptr);

    dim3 gAttn(SEQ / 128, BATCH * NHEADS);
    attn_mma_kernel<<<gAttn, 256, ATTN_SMEM>>>();

    dim3 gProj(MTOT / BM, DMODEL / BN);
    mma_gemm<1><<<gProj, 256, GEMM_SMEM>>>(bo, nullptr, nullptr, out);
}

// round 6
// speedup vs baseline: 5.7057x; 1.1362x over previous
#include <cuda_runtime.h>
#include <cuda_fp16.h>
#include <cstdint>
#include <math.h>

#define DMODEL 1024
#define NHEADS 16
#define DK     64
#define BATCH  4
#define SEQ    2048
#define MTOT   (BATCH*SEQ)   // 8192

#define QSCALE 0.1803368801111204f   // 0.125 * log2(e)

// ---------------- device scratch (allocation-free) ----------------
__device__ __half g_Qh[(size_t)MTOT * DMODEL];  // [B*H][S][DK]
__device__ __half g_Ql[(size_t)MTOT * DMODEL];
__device__ __half g_Kh[(size_t)MTOT * DMODEL];  // hi only
__device__ __half g_Vh[(size_t)MTOT * DMODEL];  // hi only
__device__ __half g_xh[(size_t)MTOT * DMODEL];
__device__ __half g_xl[(size_t)MTOT * DMODEL];
__device__ __half g_Wh[(size_t)4 * DMODEL * DMODEL];   // weights hi only
__device__ __half g_ah[(size_t)MTOT * DMODEL];  // attn out hi/lo [B,S,H*DK]
__device__ __half g_al[(size_t)MTOT * DMODEL];

// ---------------- helpers ----------------
__device__ __forceinline__ uint32_t smem_u32(const void* p) {
    uint32_t a;
    asm("{ .reg .u64 t; cvta.to.shared.u64 t, %1; cvt.u32.u64 %0, t; }" : "=r"(a) : "l"(p));
    return a;
}
__device__ __forceinline__ uint32_t swz(uint32_t o) { return o ^ ((o >> 3) & 0x70); }

__device__ __forceinline__ void cp16(uint32_t dst, const void* src) {
    asm volatile("cp.async.cg.shared.global [%0], [%1], 16;" :: "r"(dst), "l"(src));
}
#define CP_COMMIT() asm volatile("cp.async.commit_group;" ::: "memory")
#define CP_WAIT0()  asm volatile("cp.async.wait_group 0;" ::: "memory")
#define CP_WAIT1()  asm volatile("cp.async.wait_group 1;" ::: "memory")

__device__ __forceinline__ void ldsm4(uint32_t* r, uint32_t a) {
    asm volatile("ldmatrix.sync.aligned.m8n8.x4.shared.b16 {%0,%1,%2,%3}, [%4];"
                 : "=r"(r[0]), "=r"(r[1]), "=r"(r[2]), "=r"(r[3]) : "r"(a));
}
__device__ __forceinline__ void ldsm4t(uint32_t* r, uint32_t a) {
    asm volatile("ldmatrix.sync.aligned.m8n8.x4.trans.shared.b16 {%0,%1,%2,%3}, [%4];"
                 : "=r"(r[0]), "=r"(r[1]), "=r"(r[2]), "=r"(r[3]) : "r"(a));
}
__device__ __forceinline__ void mma16816(float* c, const uint32_t* a, const uint32_t* b) {
    asm volatile("mma.sync.aligned.m16n8k16.row.col.f32.f16.f16.f32 "
                 "{%0,%1,%2,%3}, {%4,%5,%6,%7}, {%8,%9}, {%0,%1,%2,%3};"
                 : "+f"(c[0]), "+f"(c[1]), "+f"(c[2]), "+f"(c[3])
                 : "r"(a[0]), "r"(a[1]), "r"(a[2]), "r"(a[3]), "r"(b[0]), "r"(b[1]));
}

// Fast exp2 for t <= 0 (FMA pipe; err ~4e-5 rel)
__device__ __forceinline__ float exp2f_fast(float t) {
    t = fmaxf(t, -80.0f);
    float a = __fadd_rn(t, 12582912.0f);
    float r = __fsub_rn(t, __fsub_rn(a, 12582912.0f));
    float p = fmaf(r, 0.0096181291f, 0.0555041087f);
    p = fmaf(p, r, 0.2402265069f);
    p = fmaf(p, r, 0.6931471806f);
    p = fmaf(p, r, 1.0f);
    return __int_as_float(__float_as_int(p) + (__float_as_int(a) << 23));
}

__device__ __forceinline__ void split2(float x, float y, uint32_t& hi, uint32_t& lo) {
    __half hx = __float2half_rn(x), hy = __float2half_rn(y);
    __half2 h(hx, hy);
    hi = *reinterpret_cast<uint32_t*>(&h);
    __half2 l(__float2half_rn(x - __half2float(hx)),
              __float2half_rn(y - __half2float(hy)));
    lo = *reinterpret_cast<uint32_t*>(&l);
}
__device__ __forceinline__ void store_hl(__half* ah, __half* al,
                                         size_t idx, float x, float y) {
    __half hx = __float2half_rn(x), hy = __float2half_rn(y);
    *reinterpret_cast<__half2*>(ah + idx) = __half2(hx, hy);
    *reinterpret_cast<__half2*>(al + idx) =
        __half2(__float2half_rn(x - __half2float(hx)),
                __float2half_rn(y - __half2float(hy)));
}

// ---------------- fused split: x -> hi/lo, Wq/Wk/Wv/Wo -> hi ----------------
#define N4X (MTOT * DMODEL / 4)        // 2097152
#define N4W (DMODEL * DMODEL / 4)      // 262144
#define SPLIT_BLOCKS ((N4X + 4 * N4W) / 256)

__global__ void split_all_kernel(const float4* __restrict__ x,
                                 const float4* __restrict__ Wq,
                                 const float4* __restrict__ Wk,
                                 const float4* __restrict__ Wv,
                                 const float4* __restrict__ Wo)
{
    int gi = blockIdx.x * 256 + threadIdx.x;
    if (gi < N4X) {
        float4 v = x[gi];
        uint32_t h0, l0, h1, l1;
        split2(v.x, v.y, h0, l0);
        split2(v.z, v.w, h1, l1);
        __half2* dh = reinterpret_cast<__half2*>(g_xh);
        __half2* dl = reinterpret_cast<__half2*>(g_xl);
        dh[2 * gi + 0] = *reinterpret_cast<__half2*>(&h0);
        dh[2 * gi + 1] = *reinterpret_cast<__half2*>(&h1);
        dl[2 * gi + 0] = *reinterpret_cast<__half2*>(&l0);
        dl[2 * gi + 1] = *reinterpret_cast<__half2*>(&l1);
    } else {
        int wi = gi - N4X;
        int z = wi / N4W;
        int i = wi - z * N4W;
        const float4* src = (z == 0) ? Wq : ((z == 1) ? Wk : ((z == 2) ? Wv : Wo));
        float4 v = src[i];
        __half2* dh = reinterpret_cast<__half2*>(g_Wh + (size_t)z * DMODEL * DMODEL);
        dh[2 * i + 0] = __half2(__float2half_rn(v.x), __float2half_rn(v.y));
        dh[2 * i + 1] = __half2(__float2half_rn(v.z), __float2half_rn(v.w));
    }
}

// ---------------- fp16 mma GEMM: C = A @ W^T + b ----------------------------
// 2-term (Ah+Al)·Bh for Q and output proj; 1-term Ah·Bh for K/V.
// CTA 128x128, chunk = 64 k, 2 stages, target 2 CTAs/SM.
#define BM 128
#define BN 128
#define CHUNKS 16
#define ATILE 16384
#define STAGE_BYTES (3 * ATILE)
#define GEMM_SMEM   (2 * STAGE_BYTES)   // 96KB

template <int MODE>  // 0 = QKV, 1 = output proj
__global__ __launch_bounds__(256, 2) void mma_gemm(
    const float* __restrict__ b0, const float* __restrict__ b1,
    const float* __restrict__ b2, float* __restrict__ outp)
{
    extern __shared__ char smg[];
    const uint32_t sbase = smem_u32(smg);
    const int tid = threadIdx.x, wid = tid >> 5, lane = tid & 31;
    const int warp_m = wid & 3, warp_n = wid >> 2;
    const int m0 = blockIdx.x * BM;
    const int n0 = blockIdx.y * BN;
    const int z  = (MODE == 0) ? blockIdx.z : 3;
    const bool two = (MODE == 1) || (z == 0);   // 2-term only for Q and proj

    const __half* Ah = (MODE == 0) ? g_xh : g_ah;
    const __half* Al = (MODE == 0) ? g_xl : g_al;
    const __half* Bh = g_Wh + (size_t)z * DMODEL * DMODEL;
    const float* bias = (MODE == 0) ? ((z == 0) ? b0 : ((z == 1) ? b1 : b2)) : b0;

    float cacc[2][8][4];
#pragma unroll
    for (int mi = 0; mi < 2; mi++)
#pragma unroll
        for (int ni = 0; ni < 8; ni++)
#pragma unroll
            for (int q = 0; q < 4; q++) cacc[mi][ni][q] = 0.f;

    auto load_chunk = [&](int c, int stage) {
        const int kk = c * 64;
        const uint32_t sAh = sbase + stage * STAGE_BYTES;
        const uint32_t sAl = sAh + ATILE;
        const uint32_t sB  = sAh + 2 * ATILE;
#pragma unroll
        for (int i = 0; i < 4; i++) {
            int u = tid + i * 256;       // 0..1023
            int row = u >> 3, c16 = u & 7;
            uint32_t so = swz((uint32_t)(row * 128 + c16 * 16));
            size_t go = (size_t)row * DMODEL + kk + c16 * 8;
            cp16(sAh + so, Ah + (size_t)m0 * DMODEL + go);
            if (two) cp16(sAl + so, Al + (size_t)m0 * DMODEL + go);
            cp16(sB  + so, Bh + (size_t)n0 * DMODEL + go);
        }
    };

    load_chunk(0, 0); CP_COMMIT();

    for (int c = 0; c < CHUNKS; c++) {
        if (c + 1 < CHUNKS) { load_chunk(c + 1, (c + 1) & 1); CP_COMMIT(); CP_WAIT1(); }
        else                { CP_WAIT0(); }
        __syncthreads();

        const uint32_t sAh = sbase + (c & 1) * STAGE_BYTES;
        const uint32_t sAl = sAh + ATILE;
        const uint32_t sB  = sAh + 2 * ATILE;

#pragma unroll
        for (int ks = 0; ks < 4; ks++) {
            uint32_t ah[2][4], al[2][4], b[4][4];
#pragma unroll
            for (int mi = 0; mi < 2; mi++) {
                int r = warp_m * 32 + mi * 16 + (lane & 15);
                uint32_t so = swz((uint32_t)(r * 128 + ks * 32 + ((lane >> 4) << 4)));
                ldsm4(ah[mi], sAh + so);
                if (two) ldsm4(al[mi], sAl + so);
            }
#pragma unroll
            for (int nb = 0; nb < 4; nb++) {
                int n = warp_n * 64 + nb * 16 + (lane & 7) + ((lane >> 4) << 3);
                ldsm4(b[nb], sB + swz((uint32_t)(n * 128 + ks * 32 + (((lane >> 3) & 1) << 4))));
            }
#pragma unroll
            for (int mi = 0; mi < 2; mi++)
#pragma unroll
                for (int ni = 0; ni < 8; ni++) {
                    mma16816(cacc[mi][ni], ah[mi], &b[ni >> 1][(ni & 1) * 2]);
                    if (two) mma16816(cacc[mi][ni], al[mi], &b[ni >> 1][(ni & 1) * 2]);
                }
        }
        __syncthreads();
    }

    const int row_base = m0 + warp_m * 32 + (lane >> 2);
    const int col_base = n0 + warp_n * 64 + (lane & 3) * 2;
#pragma unroll
    for (int ni = 0; ni < 8; ni++) {
        const int cc = col_base + ni * 8;
        const float bz0 = __ldg(&bias[cc]);
        const float bz1 = __ldg(&bias[cc + 1]);
#pragma unroll
        for (int mi = 0; mi < 2; mi++) {
#pragma unroll
            for (int half = 0; half < 2; half++) {
                const int m = row_base + mi * 16 + half * 8;
                float vx = cacc[mi][ni][half * 2 + 0] + bz0;
                float vy = cacc[mi][ni][half * 2 + 1] + bz1;
                if (MODE == 0) {
                    const int bb = m >> 11, s = m & (SEQ - 1);
                    const int hd = cc >> 6, d = cc & 63;
                    size_t idx = (((size_t)(bb * NHEADS + hd)) * SEQ + s) * DK + d;
                    if (z == 0) {
                        vx *= QSCALE; vy *= QSCALE;
                        store_hl(g_Qh, g_Ql, idx, vx, vy);
                    } else if (z == 1) {
                        *reinterpret_cast<__half2*>(g_Kh + idx) =
                            __half2(__float2half_rn(vx), __float2half_rn(vy));
                    } else {
                        *reinterpret_cast<__half2*>(g_Vh + idx) =
                            __half2(__float2half_rn(vx), __float2half_rn(vy));
                    }
                } else {
                    float2 v; v.x = vx; v.y = vy;
                    *reinterpret_cast<float2*>(&outp[(size_t)m * DMODEL + cc]) = v;
                }
            }
        }
    }
}

// ---------------- tensor-core causal flash attention (fp16, 2-term) --------
#define AQ_BYTES     32768
#define ASTAGE_BYTES 16384
#define ATTN_SMEM    (AQ_BYTES + 2 * ASTAGE_BYTES)   // 64KB

__global__ __launch_bounds__(256, 1) void attn_mma_kernel()
{
    extern __shared__ char smem[];
    const uint32_t sb = smem_u32(smem);
    const int tid = threadIdx.x, wid = tid >> 5, lane = tid & 31;
    const int qi = gridDim.x - 1 - blockIdx.x;   // long tiles first
    const int bh = blockIdx.y;
    const int q0 = qi * 128;
    const size_t base = (size_t)bh * SEQ * DK;

    const uint32_t sQh = sb;
    const uint32_t sQl = sb + 16384;

#pragma unroll
    for (int i = 0; i < 4; i++) {
        int u = tid + i * 256;
        int row = u >> 3, c16 = u & 7;
        uint32_t so = swz((uint32_t)(row * 128 + c16 * 16));
        cp16(sQh + so, g_Qh + base + (size_t)(q0 + row) * DK + c16 * 8);
        cp16(sQl + so, g_Ql + base + (size_t)(q0 + row) * DK + c16 * 8);
    }
    CP_COMMIT();

    const int nkt = 2 * qi + 2;
    auto load_kv = [&](int kt) {
        uint32_t st = sb + AQ_BYTES + (uint32_t)(kt & 1) * ASTAGE_BYTES;
        const size_t ko = base + (size_t)kt * 64 * DK;
#pragma unroll
        for (int i = 0; i < 2; i++) {
            int u = tid * 2 + i;          // 0..511
            int row = u >> 3, c16 = u & 7;
            uint32_t so = swz((uint32_t)(row * 128 + c16 * 16));
            cp16(st + so,        g_Kh + ko + (size_t)row * DK + c16 * 8);
            cp16(st + 8192 + so, g_Vh + ko + (size_t)row * DK + c16 * 8);
        }
    };

    load_kv(0); CP_COMMIT();
    CP_WAIT1();               // Q ready
    __syncthreads();

    uint32_t qh[4][4], ql[4][4];
    {
        int r = wid * 16 + (lane & 15);
        uint32_t half = (uint32_t)((lane >> 4) << 4);
#pragma unroll
        for (int kc = 0; kc < 4; kc++) {
            ldsm4(qh[kc], sQh + swz((uint32_t)(r * 128 + kc * 32) + half));
            ldsm4(ql[kc], sQl + swz((uint32_t)(r * 128 + kc * 32) + half));
        }
    }

    float o[8][4];
#pragma unroll
    for (int nt = 0; nt < 8; nt++)
#pragma unroll
        for (int q = 0; q < 4; q++) o[nt][q] = 0.f;
    float m0v = -3.0e38f, m1v = -3.0e38f, l0 = 0.f, l1 = 0.f;

    const int rq = q0 + wid * 16 + (lane >> 2);

    for (int kt = 0; kt < nkt; kt++) {
        if (kt + 1 < nkt) { load_kv(kt + 1); CP_COMMIT(); CP_WAIT1(); }
        else              { CP_WAIT0(); }
        __syncthreads();

        const uint32_t st = sb + AQ_BYTES + (uint32_t)(kt & 1) * ASTAGE_BYTES;

        // ---- S = Q K^T (Qh+Ql)·Kh ----
        float s[8][4];
#pragma unroll
        for (int nt = 0; nt < 8; nt++)
#pragma unroll
            for (int q = 0; q < 4; q++) s[nt][q] = 0.f;

        const int nrow = (lane & 7) + ((lane >> 4) << 3);
        const uint32_t koff = (uint32_t)(((lane >> 3) & 1) << 4);
#pragma unroll
        for (int kc = 0; kc < 4; kc++) {
            uint32_t kb[16];
#pragma unroll
            for (int nb = 0; nb < 4; nb++)
                ldsm4(kb + nb * 4, st + swz((uint32_t)((nb * 16 + nrow) * 128 + kc * 32) + koff));
#pragma unroll
            for (int nt = 0; nt < 8; nt++) mma16816(s[nt], qh[kc], &kb[nt * 2]);
#pragma unroll
            for (int nt = 0; nt < 8; nt++) mma16816(s[nt], ql[kc], &kb[nt * 2]);
        }

        // ---- causal mask ----
        if (kt * 64 + 63 > q0 + wid * 16) {
            const int cb = kt * 64 + 2 * (lane & 3);
#pragma unroll
            for (int nt = 0; nt < 8; nt++) {
                int c0 = cb + 8 * nt;
                if (c0     > rq)     s[nt][0] = -1.0e30f;
                if (c0 + 1 > rq)     s[nt][1] = -1.0e30f;
                if (c0     > rq + 8) s[nt][2] = -1.0e30f;
                if (c0 + 1 > rq + 8) s[nt][3] = -1.0e30f;
            }
        }

        // ---- online softmax ----
        float mx0 = -3.0e38f, mx1 = -3.0e38f;
#pragma unroll
        for (int nt = 0; nt < 8; nt++) {
            mx0 = fmaxf(mx0, fmaxf(s[nt][0], s[nt][1]));
            mx1 = fmaxf(mx1, fmaxf(s[nt][2], s[nt][3]));
        }
        mx0 = fmaxf(mx0, __shfl_xor_sync(0xFFFFFFFFu, mx0, 1));
        mx0 = fmaxf(mx0, __shfl_xor_sync(0xFFFFFFFFu, mx0, 2));
        mx1 = fmaxf(mx1, __shfl_xor_sync(0xFFFFFFFFu, mx1, 1));
        mx1 = fmaxf(mx1, __shfl_xor_sync(0xFFFFFFFFu, mx1, 2));
        const float mn0 = fmaxf(m0v, mx0), mn1 = fmaxf(m1v, mx1);
        const float f0 = exp2f_fast(m0v - mn0), f1 = exp2f_fast(m1v - mn1);
        m0v = mn0; m1v = mn1;

        float sum0 = 0.f, sum1 = 0.f;
        uint32_t ph[4][4], pl[4][4];
#pragma unroll
        for (int kc = 0; kc < 4; kc++) {
            float e00 = exp2f_fast(s[2*kc][0]   - mn0);
            float e01 = exp2f_fast(s[2*kc][1]   - mn0);
            float e10 = exp2f_fast(s[2*kc][2]   - mn1);
            float e11 = exp2f_fast(s[2*kc][3]   - mn1);
            float e20 = exp2f_fast(s[2*kc+1][0] - mn0);
            float e21 = exp2f_fast(s[2*kc+1][1] - mn0);
            float e30 = exp2f_fast(s[2*kc+1][2] - mn1);
            float e31 = exp2f_fast(s[2*kc+1][3] - mn1);
            sum0 += (e00 + e01) + (e20 + e21);
            sum1 += (e10 + e11) + (e30 + e31);
            split2(e00, e01, ph[kc][0], pl[kc][0]);
            split2(e10, e11, ph[kc][1], pl[kc][1]);
            split2(e20, e21, ph[kc][2], pl[kc][2]);
            split2(e30, e31, ph[kc][3], pl[kc][3]);
        }
        sum0 += __shfl_xor_sync(0xFFFFFFFFu, sum0, 1);
        sum0 += __shfl_xor_sync(0xFFFFFFFFu, sum0, 2);
        sum1 += __shfl_xor_sync(0xFFFFFFFFu, sum1, 1);
        sum1 += __shfl_xor_sync(0xFFFFFFFFu, sum1, 2);
        l0 = l0 * f0 + sum0;
        l1 = l1 * f1 + sum1;

#pragma unroll
        for (int nt = 0; nt < 8; nt++) {
            o[nt][0] *= f0; o[nt][1] *= f0;
            o[nt][2] *= f1; o[nt][3] *= f1;
        }

        // ---- O += (Ph+Pl)·Vh ----
        const int vkey = ((lane >> 3) & 1) * 8 + (lane & 7);
        const uint32_t vdk = (uint32_t)(((lane >> 4) << 3) * 2);
#pragma unroll
        for (int kc = 0; kc < 4; kc++) {
            uint32_t vb[16];
#pragma unroll
            for (int p4 = 0; p4 < 4; p4++)
                ldsm4t(vb + p4 * 4, st + 8192 +
                       swz((uint32_t)((kc * 16 + vkey) * 128 + p4 * 32) + vdk));
#pragma unroll
            for (int nt = 0; nt < 8; nt++) mma16816(o[nt], ph[kc], &vb[nt * 2]);
#pragma unroll
            for (int nt = 0; nt < 8; nt++) mma16816(o[nt], pl[kc], &vb[nt * 2]);
        }
        __syncthreads();
    }

    // ---- epilogue ----
    const float inv0 = 1.0f / l0, inv1 = 1.0f / l1;
    const int b = bh >> 4, hd = bh & 15;
    const int dkb = 2 * (lane & 3);
#pragma unroll
    for (int nt = 0; nt < 8; nt++) {
        const int d = hd * 64 + dkb + 8 * nt;
        size_t i0 = ((size_t)b * SEQ + rq) * DMODEL + d;
        size_t i1 = ((size_t)b * SEQ + rq + 8) * DMODEL + d;
        store_hl(g_ah, g_al, i0, o[nt][0] * inv0, o[nt][1] * inv0);
        store_hl(g_ah, g_al, i1, o[nt][2] * inv1, o[nt][3] * inv1);
    }
}

// ---------------------------------------------------------------------------
extern "C" void kernel_launch(void* const* d_in, const int* in_sizes, int n_in,
                              void* d_out, int out_size)
{
    const float* x  = (const float*)d_in[0];
    const float* Wq = (const float*)d_in[1];
    const float* bq = (const float*)d_in[2];
    const float* Wk = (const float*)d_in[3];
    const float* bk = (const float*)d_in[4];
    const float* Wv = (const float*)d_in[5];
    const float* bv = (const float*)d_in[6];
    const float* Wo = (const float*)d_in[7];
    const float* bo = (const float*)d_in[8];
    float* out = (float*)d_out;
    (void)in_sizes; (void)n_in; (void)out_size;

    static bool attr_done = false;
    if (!attr_done) {
        cudaFuncSetAttribute(mma_gemm<0>, cudaFuncAttributeMaxDynamicSharedMemorySize, GEMM_SMEM);
        cudaFuncSetAttribute(mma_gemm<1>, cudaFuncAttributeMaxDynamicSharedMemorySize, GEMM_SMEM);
        cudaFuncSetAttribute(attn_mma_kernel, cudaFuncAttributeMaxDynamicSharedMemorySize, ATTN_SMEM);
        attr_done = true;
    }

    split_all_kernel<<<SPLIT_BLOCKS, 256>>>((const float4*)x, (const float4*)Wq,
                                            (const float4*)Wk, (const float4*)Wv,
                                            (const float4*)Wo);

    dim3 gQKV(MTOT / BM, DMODEL / BN, 3);
    mma_gemm<0><<<gQKV, 256, GEMM_SMEM>>>(bq, bk, bv, nullptr);

    dim3 gAttn(SEQ / 128, BATCH * NHEADS);
    attn_mma_kernel<<<gAttn, 256, ATTN_SMEM>>>();

    dim3 gProj(MTOT / BM, DMODEL / BN);
    mma_gemm<1><<<gProj, 256, GEMM_SMEM>>>(bo, nullptr, nullptr, out);
}

// round 7
// speedup vs baseline: 6.0802x; 1.0656x over previous
#include <cuda_runtime.h>
#include <cuda_fp16.h>
#include <cstdint>
#include <math.h>

#define DMODEL 1024
#define NHEADS 16
#define DK     64
#define BATCH  4
#define SEQ    2048
#define MTOT   (BATCH*SEQ)   // 8192

#define QSCALE 0.1803368801111204f   // 0.125 * log2(e)

// ---------------- device scratch (allocation-free) ----------------
__device__ __half g_Qh[(size_t)MTOT * DMODEL];  // [B*H][S][DK]
__device__ __half g_Ql[(size_t)MTOT * DMODEL];
__device__ __half g_Kh[(size_t)MTOT * DMODEL];  // hi only
__device__ __half g_Vh[(size_t)MTOT * DMODEL];  // hi only
__device__ __half g_xh[(size_t)MTOT * DMODEL];
__device__ __half g_xl[(size_t)MTOT * DMODEL];
__device__ __half g_Wh[(size_t)4 * DMODEL * DMODEL];   // weights hi only
__device__ __half g_ah[(size_t)MTOT * DMODEL];  // attn out hi/lo [B,S,H*DK]
__device__ __half g_al[(size_t)MTOT * DMODEL];

// ---------------- helpers ----------------
__device__ __forceinline__ uint32_t smem_u32(const void* p) {
    uint32_t a;
    asm("{ .reg .u64 t; cvta.to.shared.u64 t, %1; cvt.u32.u64 %0, t; }" : "=r"(a) : "l"(p));
    return a;
}
__device__ __forceinline__ uint32_t swz(uint32_t o) { return o ^ ((o >> 3) & 0x70); }

__device__ __forceinline__ void cp16(uint32_t dst, const void* src) {
    asm volatile("cp.async.cg.shared.global [%0], [%1], 16;" :: "r"(dst), "l"(src));
}
#define CP_COMMIT() asm volatile("cp.async.commit_group;" ::: "memory")
#define CP_WAIT0()  asm volatile("cp.async.wait_group 0;" ::: "memory")
#define CP_WAIT1()  asm volatile("cp.async.wait_group 1;" ::: "memory")

__device__ __forceinline__ void ldsm4(uint32_t* r, uint32_t a) {
    asm volatile("ldmatrix.sync.aligned.m8n8.x4.shared.b16 {%0,%1,%2,%3}, [%4];"
                 : "=r"(r[0]), "=r"(r[1]), "=r"(r[2]), "=r"(r[3]) : "r"(a));
}
__device__ __forceinline__ void ldsm4t(uint32_t* r, uint32_t a) {
    asm volatile("ldmatrix.sync.aligned.m8n8.x4.trans.shared.b16 {%0,%1,%2,%3}, [%4];"
                 : "=r"(r[0]), "=r"(r[1]), "=r"(r[2]), "=r"(r[3]) : "r"(a));
}
__device__ __forceinline__ void mma16816(float* c, const uint32_t* a, const uint32_t* b) {
    asm volatile("mma.sync.aligned.m16n8k16.row.col.f32.f16.f16.f32 "
                 "{%0,%1,%2,%3}, {%4,%5,%6,%7}, {%8,%9}, {%0,%1,%2,%3};"
                 : "+f"(c[0]), "+f"(c[1]), "+f"(c[2]), "+f"(c[3])
                 : "r"(a[0]), "r"(a[1]), "r"(a[2]), "r"(a[3]), "r"(b[0]), "r"(b[1]));
}

// Fast exp2 for t <= 0 (FMA pipe; err ~4e-5 rel)
__device__ __forceinline__ float exp2f_fast(float t) {
    t = fmaxf(t, -80.0f);
    float a = __fadd_rn(t, 12582912.0f);
    float r = __fsub_rn(t, __fsub_rn(a, 12582912.0f));
    float p = fmaf(r, 0.0096181291f, 0.0555041087f);
    p = fmaf(p, r, 0.2402265069f);
    p = fmaf(p, r, 0.6931471806f);
    p = fmaf(p, r, 1.0f);
    return __int_as_float(__float_as_int(p) + (__float_as_int(a) << 23));
}

__device__ __forceinline__ void split2(float x, float y, uint32_t& hi, uint32_t& lo) {
    __half hx = __float2half_rn(x), hy = __float2half_rn(y);
    __half2 h(hx, hy);
    hi = *reinterpret_cast<uint32_t*>(&h);
    __half2 l(__float2half_rn(x - __half2float(hx)),
              __float2half_rn(y - __half2float(hy)));
    lo = *reinterpret_cast<uint32_t*>(&l);
}
__device__ __forceinline__ uint32_t pack2(float x, float y) {
    __half2 h = __floats2half2_rn(x, y);
    return *reinterpret_cast<uint32_t*>(&h);
}
__device__ __forceinline__ void store_hl(__half* ah, __half* al,
                                         size_t idx, float x, float y) {
    __half hx = __float2half_rn(x), hy = __float2half_rn(y);
    *reinterpret_cast<__half2*>(ah + idx) = __half2(hx, hy);
    *reinterpret_cast<__half2*>(al + idx) =
        __half2(__float2half_rn(x - __half2float(hx)),
                __float2half_rn(y - __half2float(hy)));
}

// ---------------- fused split: x -> hi/lo, Wq/Wk/Wv/Wo -> hi ----------------
#define N4X (MTOT * DMODEL / 4)        // 2097152
#define N4W (DMODEL * DMODEL / 4)      // 262144
#define SPLIT_BLOCKS ((N4X + 4 * N4W) / 256)

__global__ void split_all_kernel(const float4* __restrict__ x,
                                 const float4* __restrict__ Wq,
                                 const float4* __restrict__ Wk,
                                 const float4* __restrict__ Wv,
                                 const float4* __restrict__ Wo)
{
    int gi = blockIdx.x * 256 + threadIdx.x;
    if (gi < N4X) {
        float4 v = x[gi];
        uint32_t h0, l0, h1, l1;
        split2(v.x, v.y, h0, l0);
        split2(v.z, v.w, h1, l1);
        __half2* dh = reinterpret_cast<__half2*>(g_xh);
        __half2* dl = reinterpret_cast<__half2*>(g_xl);
        dh[2 * gi + 0] = *reinterpret_cast<__half2*>(&h0);
        dh[2 * gi + 1] = *reinterpret_cast<__half2*>(&h1);
        dl[2 * gi + 0] = *reinterpret_cast<__half2*>(&l0);
        dl[2 * gi + 1] = *reinterpret_cast<__half2*>(&l1);
    } else {
        int wi = gi - N4X;
        int z = wi / N4W;
        int i = wi - z * N4W;
        const float4* src = (z == 0) ? Wq : ((z == 1) ? Wk : ((z == 2) ? Wv : Wo));
        float4 v = src[i];
        __half2* dh = reinterpret_cast<__half2*>(g_Wh + (size_t)z * DMODEL * DMODEL);
        dh[2 * i + 0] = __half2(__float2half_rn(v.x), __float2half_rn(v.y));
        dh[2 * i + 1] = __half2(__float2half_rn(v.z), __float2half_rn(v.w));
    }
}

// ---------------- fp16 mma GEMM: C = A @ W^T + b ----------------------------
// 2-term (Ah+Al)·Bh for Q and output proj; 1-term for K/V.
// CTA 128x128, chunk 64 k, 2 stages, one __syncthreads per chunk, 2 CTAs/SM.
#define BM 128
#define BN 128
#define CHUNKS 16
#define ATILE 16384
#define STAGE_BYTES (3 * ATILE)
#define GEMM_SMEM   (2 * STAGE_BYTES)   // 96KB

template <int MODE>  // 0 = QKV, 1 = output proj
__global__ __launch_bounds__(256, 2) void mma_gemm(
    const float* __restrict__ b0, const float* __restrict__ b1,
    const float* __restrict__ b2, float* __restrict__ outp)
{
    extern __shared__ char smg[];
    const uint32_t sbase = smem_u32(smg);
    const int tid = threadIdx.x, wid = tid >> 5, lane = tid & 31;
    const int warp_m = wid & 3, warp_n = wid >> 2;
    const int m0 = blockIdx.x * BM;
    const int n0 = blockIdx.y * BN;
    const int z  = (MODE == 0) ? blockIdx.z : 3;
    const bool two = (MODE == 1) || (z == 0);

    const __half* Ah = (MODE == 0) ? g_xh : g_ah;
    const __half* Al = (MODE == 0) ? g_xl : g_al;
    const __half* Bh = g_Wh + (size_t)z * DMODEL * DMODEL;
    const float* bias = (MODE == 0) ? ((z == 0) ? b0 : ((z == 1) ? b1 : b2)) : b0;

    float cacc[2][8][4];
#pragma unroll
    for (int mi = 0; mi < 2; mi++)
#pragma unroll
        for (int ni = 0; ni < 8; ni++)
#pragma unroll
            for (int q = 0; q < 4; q++) cacc[mi][ni][q] = 0.f;

    auto load_chunk = [&](int c, int stage) {
        const int kk = c * 64;
        const uint32_t sAh = sbase + stage * STAGE_BYTES;
        const uint32_t sAl = sAh + ATILE;
        const uint32_t sB  = sAh + 2 * ATILE;
#pragma unroll
        for (int i = 0; i < 4; i++) {
            int u = tid + i * 256;       // 0..1023
            int row = u >> 3, c16 = u & 7;
            uint32_t so = swz((uint32_t)(row * 128 + c16 * 16));
            size_t go = (size_t)row * DMODEL + kk + c16 * 8;
            cp16(sAh + so, Ah + (size_t)m0 * DMODEL + go);
            if (two) cp16(sAl + so, Al + (size_t)m0 * DMODEL + go);
            cp16(sB  + so, Bh + (size_t)n0 * DMODEL + go);
        }
    };

    load_chunk(0, 0); CP_COMMIT();

    for (int c = 0; c < CHUNKS; c++) {
        // Wait for chunk c (only group possibly outstanding), make visible.
        CP_WAIT0();
        __syncthreads();
        // Prefetch c+1 into the stage consumed at c-1 (safe: all warps past sync).
        if (c + 1 < CHUNKS) { load_chunk(c + 1, (c + 1) & 1); CP_COMMIT(); }

        const uint32_t sAh = sbase + (c & 1) * STAGE_BYTES;
        const uint32_t sAl = sAh + ATILE;
        const uint32_t sB  = sAh + 2 * ATILE;

#pragma unroll
        for (int ks = 0; ks < 4; ks++) {
            uint32_t ah[2][4], al[2][4], b[4][4];
#pragma unroll
            for (int mi = 0; mi < 2; mi++) {
                int r = warp_m * 32 + mi * 16 + (lane & 15);
                uint32_t so = swz((uint32_t)(r * 128 + ks * 32 + ((lane >> 4) << 4)));
                ldsm4(ah[mi], sAh + so);
                if (two) ldsm4(al[mi], sAl + so);
            }
#pragma unroll
            for (int nb = 0; nb < 4; nb++) {
                int n = warp_n * 64 + nb * 16 + (lane & 7) + ((lane >> 4) << 3);
                ldsm4(b[nb], sB + swz((uint32_t)(n * 128 + ks * 32 + (((lane >> 3) & 1) << 4))));
            }
#pragma unroll
            for (int mi = 0; mi < 2; mi++)
#pragma unroll
                for (int ni = 0; ni < 8; ni++) {
                    mma16816(cacc[mi][ni], ah[mi], &b[ni >> 1][(ni & 1) * 2]);
                    if (two) mma16816(cacc[mi][ni], al[mi], &b[ni >> 1][(ni & 1) * 2]);
                }
        }
    }

    const int row_base = m0 + warp_m * 32 + (lane >> 2);
    const int col_base = n0 + warp_n * 64 + (lane & 3) * 2;
#pragma unroll
    for (int ni = 0; ni < 8; ni++) {
        const int cc = col_base + ni * 8;
        const float bz0 = __ldg(&bias[cc]);
        const float bz1 = __ldg(&bias[cc + 1]);
#pragma unroll
        for (int mi = 0; mi < 2; mi++) {
#pragma unroll
            for (int half = 0; half < 2; half++) {
                const int m = row_base + mi * 16 + half * 8;
                float vx = cacc[mi][ni][half * 2 + 0] + bz0;
                float vy = cacc[mi][ni][half * 2 + 1] + bz1;
                if (MODE == 0) {
                    const int bb = m >> 11, s = m & (SEQ - 1);
                    const int hd = cc >> 6, d = cc & 63;
                    size_t idx = (((size_t)(bb * NHEADS + hd)) * SEQ + s) * DK + d;
                    if (z == 0) {
                        vx *= QSCALE; vy *= QSCALE;
                        store_hl(g_Qh, g_Ql, idx, vx, vy);
                    } else if (z == 1) {
                        *reinterpret_cast<__half2*>(g_Kh + idx) =
                            __half2(__float2half_rn(vx), __float2half_rn(vy));
                    } else {
                        *reinterpret_cast<__half2*>(g_Vh + idx) =
                            __half2(__float2half_rn(vx), __float2half_rn(vy));
                    }
                } else {
                    float2 v; v.x = vx; v.y = vy;
                    *reinterpret_cast<float2*>(&outp[(size_t)m * DMODEL + cc]) = v;
                }
            }
        }
    }
}

// ---------------- tensor-core causal flash attention (fp16) -----------------
// Q tile 128 (Qh+Ql), KV tile 64, 3 KV stages, one sync per tile, PV 1-term.
#define AQ_BYTES     32768
#define ASTAGE_BYTES 16384
#define ATTN_SMEM    (AQ_BYTES + 3 * ASTAGE_BYTES)   // 80KB

__global__ __launch_bounds__(256, 1) void attn_mma_kernel()
{
    extern __shared__ char smem[];
    const uint32_t sb = smem_u32(smem);
    const int tid = threadIdx.x, wid = tid >> 5, lane = tid & 31;
    const int qi = gridDim.x - 1 - blockIdx.x;   // long tiles first
    const int bh = blockIdx.y;
    const int q0 = qi * 128;
    const size_t base = (size_t)bh * SEQ * DK;

    const uint32_t sQh = sb;
    const uint32_t sQl = sb + 16384;

#pragma unroll
    for (int i = 0; i < 4; i++) {
        int u = tid + i * 256;
        int row = u >> 3, c16 = u & 7;
        uint32_t so = swz((uint32_t)(row * 128 + c16 * 16));
        cp16(sQh + so, g_Qh + base + (size_t)(q0 + row) * DK + c16 * 8);
        cp16(sQl + so, g_Ql + base + (size_t)(q0 + row) * DK + c16 * 8);
    }
    CP_COMMIT();                                   // gQ

    const int nkt = 2 * qi + 2;                    // >= 2
    auto load_kv = [&](int kt) {
        uint32_t st = sb + AQ_BYTES + (uint32_t)(kt % 3) * ASTAGE_BYTES;
        const size_t ko = base + (size_t)kt * 64 * DK;
#pragma unroll
        for (int i = 0; i < 2; i++) {
            int u = tid * 2 + i;          // 0..511
            int row = u >> 3, c16 = u & 7;
            uint32_t so = swz((uint32_t)(row * 128 + c16 * 16));
            cp16(st + so,        g_Kh + ko + (size_t)row * DK + c16 * 8);
            cp16(st + 8192 + so, g_Vh + ko + (size_t)row * DK + c16 * 8);
        }
    };

    load_kv(0); CP_COMMIT();                       // g0
    load_kv(1); CP_COMMIT();                       // g1
    CP_WAIT1();                                    // gQ, g0 done
    __syncthreads();

    uint32_t qh[4][4], ql[4][4];
    {
        int r = wid * 16 + (lane & 15);
        uint32_t half = (uint32_t)((lane >> 4) << 4);
#pragma unroll
        for (int kc = 0; kc < 4; kc++) {
            ldsm4(qh[kc], sQh + swz((uint32_t)(r * 128 + kc * 32) + half));
            ldsm4(ql[kc], sQl + swz((uint32_t)(r * 128 + kc * 32) + half));
        }
    }

    float o[8][4];
#pragma unroll
    for (int nt = 0; nt < 8; nt++)
#pragma unroll
        for (int q = 0; q < 4; q++) o[nt][q] = 0.f;
    float m0v = -3.0e38f, m1v = -3.0e38f, l0 = 0.f, l1 = 0.f;

    const int rq = q0 + wid * 16 + (lane >> 2);

    for (int kt = 0; kt < nkt; kt++) {
        if (kt > 0) {
            if (kt + 1 < nkt) CP_WAIT1(); else CP_WAIT0();
            __syncthreads();
        }
        if (kt + 2 < nkt) { load_kv(kt + 2); CP_COMMIT(); }

        const uint32_t st = sb + AQ_BYTES + (uint32_t)(kt % 3) * ASTAGE_BYTES;

        // ---- S = (Qh+Ql)·Kh ----
        float s[8][4];
#pragma unroll
        for (int nt = 0; nt < 8; nt++)
#pragma unroll
            for (int q = 0; q < 4; q++) s[nt][q] = 0.f;

        const int nrow = (lane & 7) + ((lane >> 4) << 3);
        const uint32_t koff = (uint32_t)(((lane >> 3) & 1) << 4);
#pragma unroll
        for (int kc = 0; kc < 4; kc++) {
            uint32_t kb[16];
#pragma unroll
            for (int nb = 0; nb < 4; nb++)
                ldsm4(kb + nb * 4, st + swz((uint32_t)((nb * 16 + nrow) * 128 + kc * 32) + koff));
#pragma unroll
            for (int nt = 0; nt < 8; nt++) mma16816(s[nt], qh[kc], &kb[nt * 2]);
#pragma unroll
            for (int nt = 0; nt < 8; nt++) mma16816(s[nt], ql[kc], &kb[nt * 2]);
        }

        // ---- causal mask ----
        if (kt * 64 + 63 > q0 + wid * 16) {
            const int cb = kt * 64 + 2 * (lane & 3);
#pragma unroll
            for (int nt = 0; nt < 8; nt++) {
                int c0 = cb + 8 * nt;
                if (c0     > rq)     s[nt][0] = -1.0e30f;
                if (c0 + 1 > rq)     s[nt][1] = -1.0e30f;
                if (c0     > rq + 8) s[nt][2] = -1.0e30f;
                if (c0 + 1 > rq + 8) s[nt][3] = -1.0e30f;
            }
        }

        // ---- online softmax ----
        float mx0 = -3.0e38f, mx1 = -3.0e38f;
#pragma unroll
        for (int nt = 0; nt < 8; nt++) {
            mx0 = fmaxf(mx0, fmaxf(s[nt][0], s[nt][1]));
            mx1 = fmaxf(mx1, fmaxf(s[nt][2], s[nt][3]));
        }
        mx0 = fmaxf(mx0, __shfl_xor_sync(0xFFFFFFFFu, mx0, 1));
        mx0 = fmaxf(mx0, __shfl_xor_sync(0xFFFFFFFFu, mx0, 2));
        mx1 = fmaxf(mx1, __shfl_xor_sync(0xFFFFFFFFu, mx1, 1));
        mx1 = fmaxf(mx1, __shfl_xor_sync(0xFFFFFFFFu, mx1, 2));
        const float mn0 = fmaxf(m0v, mx0), mn1 = fmaxf(m1v, mx1);
        const float f0 = exp2f_fast(m0v - mn0), f1 = exp2f_fast(m1v - mn1);
        m0v = mn0; m1v = mn1;

        float sum0 = 0.f, sum1 = 0.f;
        uint32_t ph[4][4];
#pragma unroll
        for (int kc = 0; kc < 4; kc++) {
            float e00 = exp2f_fast(s[2*kc][0]   - mn0);
            float e01 = exp2f_fast(s[2*kc][1]   - mn0);
            float e10 = exp2f_fast(s[2*kc][2]   - mn1);
            float e11 = exp2f_fast(s[2*kc][3]   - mn1);
            float e20 = exp2f_fast(s[2*kc+1][0] - mn0);
            float e21 = exp2f_fast(s[2*kc+1][1] - mn0);
            float e30 = exp2f_fast(s[2*kc+1][2] - mn1);
            float e31 = exp2f_fast(s[2*kc+1][3] - mn1);
            sum0 += (e00 + e01) + (e20 + e21);
            sum1 += (e10 + e11) + (e30 + e31);
            ph[kc][0] = pack2(e00, e01);
            ph[kc][1] = pack2(e10, e11);
            ph[kc][2] = pack2(e20, e21);
            ph[kc][3] = pack2(e30, e31);
        }
        sum0 += __shfl_xor_sync(0xFFFFFFFFu, sum0, 1);
        sum0 += __shfl_xor_sync(0xFFFFFFFFu, sum0, 2);
        sum1 += __shfl_xor_sync(0xFFFFFFFFu, sum1, 1);
        sum1 += __shfl_xor_sync(0xFFFFFFFFu, sum1, 2);
        l0 = l0 * f0 + sum0;
        l1 = l1 * f1 + sum1;

#pragma unroll
        for (int nt = 0; nt < 8; nt++) {
            o[nt][0] *= f0; o[nt][1] *= f0;
            o[nt][2] *= f1; o[nt][3] *= f1;
        }

        // ---- O += Ph·Vh (1-term) ----
        const int vkey = ((lane >> 3) & 1) * 8 + (lane & 7);
        const uint32_t vdk = (uint32_t)(((lane >> 4) << 3) * 2);
#pragma unroll
        for (int kc = 0; kc < 4; kc++) {
            uint32_t vb[16];
#pragma unroll
            for (int p4 = 0; p4 < 4; p4++)
                ldsm4t(vb + p4 * 4, st + 8192 +
                       swz((uint32_t)((kc * 16 + vkey) * 128 + p4 * 32) + vdk));
#pragma unroll
            for (int nt = 0; nt < 8; nt++) mma16816(o[nt], ph[kc], &vb[nt * 2]);
        }
    }

    // ---- epilogue ----
    const float inv0 = 1.0f / l0, inv1 = 1.0f / l1;
    const int b = bh >> 4, hd = bh & 15;
    const int dkb = 2 * (lane & 3);
#pragma unroll
    for (int nt = 0; nt < 8; nt++) {
        const int d = hd * 64 + dkb + 8 * nt;
        size_t i0 = ((size_t)b * SEQ + rq) * DMODEL + d;
        size_t i1 = ((size_t)b * SEQ + rq + 8) * DMODEL + d;
        store_hl(g_ah, g_al, i0, o[nt][0] * inv0, o[nt][1] * inv0);
        store_hl(g_ah, g_al, i1, o[nt][2] * inv1, o[nt][3] * inv1);
    }
}

// ---------------------------------------------------------------------------
extern "C" void kernel_launch(void* const* d_in, const int* in_sizes, int n_in,
                              void* d_out, int out_size)
{
    const float* x  = (const float*)d_in[0];
    const float* Wq = (const float*)d_in[1];
    const float* bq = (const float*)d_in[2];
    const float* Wk = (const float*)d_in[3];
    const float* bk = (const float*)d_in[4];
    const float* Wv = (const float*)d_in[5];
    const float* bv = (const float*)d_in[6];
    const float* Wo = (const float*)d_in[7];
    const float* bo = (const float*)d_in[8];
    float* out = (float*)d_out;
    (void)in_sizes; (void)n_in; (void)out_size;

    static bool attr_done = false;
    if (!attr_done) {
        cudaFuncSetAttribute(mma_gemm<0>, cudaFuncAttributeMaxDynamicSharedMemorySize, GEMM_SMEM);
        cudaFuncSetAttribute(mma_gemm<1>, cudaFuncAttributeMaxDynamicSharedMemorySize, GEMM_SMEM);
        cudaFuncSetAttribute(attn_mma_kernel, cudaFuncAttributeMaxDynamicSharedMemorySize, ATTN_SMEM);
        attr_done = true;
    }

    split_all_kernel<<<SPLIT_BLOCKS, 256>>>((const float4*)x, (const float4*)Wq,
                                            (const float4*)Wk, (const float4*)Wv,
                                            (const float4*)Wo);

    dim3 gQKV(MTOT / BM, DMODEL / BN, 3);
    mma_gemm<0><<<gQKV, 256, GEMM_SMEM>>>(bq, bk, bv, nullptr);

    dim3 gAttn(SEQ / 128, BATCH * NHEADS);
    attn_mma_kernel<<<gAttn, 256, ATTN_SMEM>>>();

    dim3 gProj(MTOT / BM, DMODEL / BN);
    mma_gemm<1><<<gProj, 256, GEMM_SMEM>>>(bo, nullptr, nullptr, out);
}

// round 8
// speedup vs baseline: 6.5224x; 1.0727x over previous
#include <cuda_runtime.h>
#include <cuda_fp16.h>
#include <cstdint>
#include <math.h>

#define DMODEL 1024
#define NHEADS 16
#define DK     64
#define BATCH  4
#define SEQ    2048
#define MTOT   (BATCH*SEQ)   // 8192

#define QSCALE 0.1803368801111204f   // 0.125 * log2(e)

// ---------------- device scratch (allocation-free) ----------------
__device__ __half g_Qh[(size_t)MTOT * DMODEL];  // [B*H][S][DK]
__device__ __half g_Ql[(size_t)MTOT * DMODEL];
__device__ __half g_Kh[(size_t)MTOT * DMODEL];  // hi only
__device__ __half g_Vh[(size_t)MTOT * DMODEL];  // hi only
__device__ __half g_xh[(size_t)MTOT * DMODEL];
__device__ __half g_xl[(size_t)MTOT * DMODEL];
__device__ __half g_Wh[(size_t)4 * DMODEL * DMODEL];   // weights hi only
__device__ __half g_ah[(size_t)MTOT * DMODEL];  // attn out (hi only) [B,S,H*DK]

// ---------------- helpers ----------------
__device__ __forceinline__ uint32_t smem_u32(const void* p) {
    uint32_t a;
    asm("{ .reg .u64 t; cvta.to.shared.u64 t, %1; cvt.u32.u64 %0, t; }" : "=r"(a) : "l"(p));
    return a;
}
__device__ __forceinline__ uint32_t swz(uint32_t o) { return o ^ ((o >> 3) & 0x70); }

__device__ __forceinline__ void cp16(uint32_t dst, const void* src) {
    asm volatile("cp.async.cg.shared.global [%0], [%1], 16;" :: "r"(dst), "l"(src));
}
#define CP_COMMIT() asm volatile("cp.async.commit_group;" ::: "memory")
#define CP_WAIT0()  asm volatile("cp.async.wait_group 0;" ::: "memory")
#define CP_WAIT1()  asm volatile("cp.async.wait_group 1;" ::: "memory")
#define CP_WAIT2()  asm volatile("cp.async.wait_group 2;" ::: "memory")

__device__ __forceinline__ void ldsm4(uint32_t* r, uint32_t a) {
    asm volatile("ldmatrix.sync.aligned.m8n8.x4.shared.b16 {%0,%1,%2,%3}, [%4];"
                 : "=r"(r[0]), "=r"(r[1]), "=r"(r[2]), "=r"(r[3]) : "r"(a));
}
__device__ __forceinline__ void ldsm4t(uint32_t* r, uint32_t a) {
    asm volatile("ldmatrix.sync.aligned.m8n8.x4.trans.shared.b16 {%0,%1,%2,%3}, [%4];"
                 : "=r"(r[0]), "=r"(r[1]), "=r"(r[2]), "=r"(r[3]) : "r"(a));
}
__device__ __forceinline__ void mma16816(float* c, const uint32_t* a, const uint32_t* b) {
    asm volatile("mma.sync.aligned.m16n8k16.row.col.f32.f16.f16.f32 "
                 "{%0,%1,%2,%3}, {%4,%5,%6,%7}, {%8,%9}, {%0,%1,%2,%3};"
                 : "+f"(c[0]), "+f"(c[1]), "+f"(c[2]), "+f"(c[3])
                 : "r"(a[0]), "r"(a[1]), "r"(a[2]), "r"(a[3]), "r"(b[0]), "r"(b[1]));
}

// Fast exp2 for t <= 0 (FMA pipe; err ~4e-5 rel)
__device__ __forceinline__ float exp2f_fast(float t) {
    t = fmaxf(t, -80.0f);
    float a = __fadd_rn(t, 12582912.0f);
    float r = __fsub_rn(t, __fsub_rn(a, 12582912.0f));
    float p = fmaf(r, 0.0096181291f, 0.0555041087f);
    p = fmaf(p, r, 0.2402265069f);
    p = fmaf(p, r, 0.6931471806f);
    p = fmaf(p, r, 1.0f);
    return __int_as_float(__float_as_int(p) + (__float_as_int(a) << 23));
}

__device__ __forceinline__ void split2(float x, float y, uint32_t& hi, uint32_t& lo) {
    __half hx = __float2half_rn(x), hy = __float2half_rn(y);
    __half2 h(hx, hy);
    hi = *reinterpret_cast<uint32_t*>(&h);
    __half2 l(__float2half_rn(x - __half2float(hx)),
              __float2half_rn(y - __half2float(hy)));
    lo = *reinterpret_cast<uint32_t*>(&l);
}
__device__ __forceinline__ uint32_t pack2(float x, float y) {
    __half2 h = __floats2half2_rn(x, y);
    return *reinterpret_cast<uint32_t*>(&h);
}

// ---------------- fused split: x -> hi/lo, Wq/Wk/Wv/Wo -> hi ----------------
#define N4X (MTOT * DMODEL / 4)        // 2097152
#define N4W (DMODEL * DMODEL / 4)      // 262144
#define SPLIT_BLOCKS ((N4X + 4 * N4W) / 256)

__global__ void split_all_kernel(const float4* __restrict__ x,
                                 const float4* __restrict__ Wq,
                                 const float4* __restrict__ Wk,
                                 const float4* __restrict__ Wv,
                                 const float4* __restrict__ Wo)
{
    int gi = blockIdx.x * 256 + threadIdx.x;
    if (gi < N4X) {
        float4 v = x[gi];
        uint32_t h0, l0, h1, l1;
        split2(v.x, v.y, h0, l0);
        split2(v.z, v.w, h1, l1);
        __half2* dh = reinterpret_cast<__half2*>(g_xh);
        __half2* dl = reinterpret_cast<__half2*>(g_xl);
        dh[2 * gi + 0] = *reinterpret_cast<__half2*>(&h0);
        dh[2 * gi + 1] = *reinterpret_cast<__half2*>(&h1);
        dl[2 * gi + 0] = *reinterpret_cast<__half2*>(&l0);
        dl[2 * gi + 1] = *reinterpret_cast<__half2*>(&l1);
    } else {
        int wi = gi - N4X;
        int z = wi / N4W;
        int i = wi - z * N4W;
        const float4* src = (z == 0) ? Wq : ((z == 1) ? Wk : ((z == 2) ? Wv : Wo));
        float4 v = src[i];
        __half2* dh = reinterpret_cast<__half2*>(g_Wh + (size_t)z * DMODEL * DMODEL);
        dh[2 * i + 0] = __half2(__float2half_rn(v.x), __float2half_rn(v.y));
        dh[2 * i + 1] = __half2(__float2half_rn(v.z), __float2half_rn(v.w));
    }
}

// ---------------- fp16 mma GEMM: C = A @ W^T + b ----------------------------
// 2-term (Ah+Al)·Bh only for the Q projection; 1-term elsewhere.
#define BM 128
#define BN 128
#define CHUNKS 16
#define ATILE 16384
#define STAGE_BYTES (3 * ATILE)
#define GEMM_SMEM   (2 * STAGE_BYTES)   // 96KB

template <int MODE>  // 0 = QKV, 1 = output proj
__global__ __launch_bounds__(256, 2) void mma_gemm(
    const float* __restrict__ b0, const float* __restrict__ b1,
    const float* __restrict__ b2, float* __restrict__ outp)
{
    extern __shared__ char smg[];
    const uint32_t sbase = smem_u32(smg);
    const int tid = threadIdx.x, wid = tid >> 5, lane = tid & 31;
    const int warp_m = wid & 3, warp_n = wid >> 2;
    const int m0 = blockIdx.x * BM;
    const int n0 = blockIdx.y * BN;
    const int z  = (MODE == 0) ? blockIdx.z : 3;
    const bool two = (MODE == 0) && (z == 0);

    const __half* Ah = (MODE == 0) ? g_xh : g_ah;
    const __half* Al = g_xl;
    const __half* Bh = g_Wh + (size_t)z * DMODEL * DMODEL;
    const float* bias = (MODE == 0) ? ((z == 0) ? b0 : ((z == 1) ? b1 : b2)) : b0;

    float cacc[2][8][4];
#pragma unroll
    for (int mi = 0; mi < 2; mi++)
#pragma unroll
        for (int ni = 0; ni < 8; ni++)
#pragma unroll
            for (int q = 0; q < 4; q++) cacc[mi][ni][q] = 0.f;

    auto load_chunk = [&](int c, int stage) {
        const int kk = c * 64;
        const uint32_t sAh = sbase + stage * STAGE_BYTES;
        const uint32_t sAl = sAh + ATILE;
        const uint32_t sB  = sAh + 2 * ATILE;
#pragma unroll
        for (int i = 0; i < 4; i++) {
            int u = tid + i * 256;       // 0..1023
            int row = u >> 3, c16 = u & 7;
            uint32_t so = swz((uint32_t)(row * 128 + c16 * 16));
            size_t go = (size_t)row * DMODEL + kk + c16 * 8;
            cp16(sAh + so, Ah + (size_t)m0 * DMODEL + go);
            if (two) cp16(sAl + so, Al + (size_t)m0 * DMODEL + go);
            cp16(sB  + so, Bh + (size_t)n0 * DMODEL + go);
        }
    };

    load_chunk(0, 0); CP_COMMIT();

    for (int c = 0; c < CHUNKS; c++) {
        CP_WAIT0();
        __syncthreads();
        if (c + 1 < CHUNKS) { load_chunk(c + 1, (c + 1) & 1); CP_COMMIT(); }

        const uint32_t sAh = sbase + (c & 1) * STAGE_BYTES;
        const uint32_t sAl = sAh + ATILE;
        const uint32_t sB  = sAh + 2 * ATILE;

#pragma unroll
        for (int ks = 0; ks < 4; ks++) {
            uint32_t ah[2][4], al[2][4], b[4][4];
#pragma unroll
            for (int mi = 0; mi < 2; mi++) {
                int r = warp_m * 32 + mi * 16 + (lane & 15);
                uint32_t so = swz((uint32_t)(r * 128 + ks * 32 + ((lane >> 4) << 4)));
                ldsm4(ah[mi], sAh + so);
                if (two) ldsm4(al[mi], sAl + so);
            }
#pragma unroll
            for (int nb = 0; nb < 4; nb++) {
                int n = warp_n * 64 + nb * 16 + (lane & 7) + ((lane >> 4) << 3);
                ldsm4(b[nb], sB + swz((uint32_t)(n * 128 + ks * 32 + (((lane >> 3) & 1) << 4))));
            }
#pragma unroll
            for (int mi = 0; mi < 2; mi++)
#pragma unroll
                for (int ni = 0; ni < 8; ni++) {
                    mma16816(cacc[mi][ni], ah[mi], &b[ni >> 1][(ni & 1) * 2]);
                    if (two) mma16816(cacc[mi][ni], al[mi], &b[ni >> 1][(ni & 1) * 2]);
                }
        }
    }

    const int row_base = m0 + warp_m * 32 + (lane >> 2);
    const int col_base = n0 + warp_n * 64 + (lane & 3) * 2;
#pragma unroll
    for (int ni = 0; ni < 8; ni++) {
        const int cc = col_base + ni * 8;
        const float bz0 = __ldg(&bias[cc]);
        const float bz1 = __ldg(&bias[cc + 1]);
#pragma unroll
        for (int mi = 0; mi < 2; mi++) {
#pragma unroll
            for (int half = 0; half < 2; half++) {
                const int m = row_base + mi * 16 + half * 8;
                float vx = cacc[mi][ni][half * 2 + 0] + bz0;
                float vy = cacc[mi][ni][half * 2 + 1] + bz1;
                if (MODE == 0) {
                    const int bb = m >> 11, s = m & (SEQ - 1);
                    const int hd = cc >> 6, d = cc & 63;
                    size_t idx = (((size_t)(bb * NHEADS + hd)) * SEQ + s) * DK + d;
                    if (z == 0) {
                        vx *= QSCALE; vy *= QSCALE;
                        __half hx = __float2half_rn(vx), hy = __float2half_rn(vy);
                        *reinterpret_cast<__half2*>(g_Qh + idx) = __half2(hx, hy);
                        *reinterpret_cast<__half2*>(g_Ql + idx) =
                            __half2(__float2half_rn(vx - __half2float(hx)),
                                    __float2half_rn(vy - __half2float(hy)));
                    } else if (z == 1) {
                        *reinterpret_cast<__half2*>(g_Kh + idx) =
                            __half2(__float2half_rn(vx), __float2half_rn(vy));
                    } else {
                        *reinterpret_cast<__half2*>(g_Vh + idx) =
                            __half2(__float2half_rn(vx), __float2half_rn(vy));
                    }
                } else {
                    float2 v; v.x = vx; v.y = vy;
                    *reinterpret_cast<float2*>(&outp[(size_t)m * DMODEL + cc]) = v;
                }
            }
        }
    }
}

// ---------------- tensor-core causal flash attention (fp16) -----------------
// Q tile 128 (Qh+Ql), KV tile 64, 3 KV stages of 16KB. Qh/Ql are parked in
// stages 1/2 (dead after fragment load). 48KB smem -> 2 CTAs/SM.
#define ASTAGE_BYTES 16384
#define ATTN_SMEM    (3 * ASTAGE_BYTES)   // 48KB

__global__ __launch_bounds__(256, 2) void attn_mma_kernel()
{
    extern __shared__ char smem[];
    const uint32_t sb = smem_u32(smem);
    const int tid = threadIdx.x, wid = tid >> 5, lane = tid & 31;
    const int qi = gridDim.x - 1 - blockIdx.x;   // long tiles first
    const int bh = blockIdx.y;
    const int q0 = qi * 128;
    const size_t base = (size_t)bh * SEQ * DK;

    const int nkt = 2 * qi + 2;                   // >= 2
    auto load_kv = [&](int kt) {
        uint32_t st = sb + (uint32_t)(kt % 3) * ASTAGE_BYTES;
        const size_t ko = base + (size_t)kt * 64 * DK;
#pragma unroll
        for (int i = 0; i < 2; i++) {
            int u = tid * 2 + i;          // 0..511
            int row = u >> 3, c16 = u & 7;
            uint32_t so = swz((uint32_t)(row * 128 + c16 * 16));
            cp16(st + so,        g_Kh + ko + (size_t)row * DK + c16 * 8);
            cp16(st + 8192 + so, g_Vh + ko + (size_t)row * DK + c16 * 8);
        }
    };

    // Qh -> stage1, Ql -> stage2, kv0 -> stage0 (one group)
    const uint32_t sQh = sb + 1 * ASTAGE_BYTES;
    const uint32_t sQl = sb + 2 * ASTAGE_BYTES;
#pragma unroll
    for (int i = 0; i < 4; i++) {
        int u = tid + i * 256;
        int row = u >> 3, c16 = u & 7;
        uint32_t so = swz((uint32_t)(row * 128 + c16 * 16));
        cp16(sQh + so, g_Qh + base + (size_t)(q0 + row) * DK + c16 * 8);
        cp16(sQl + so, g_Ql + base + (size_t)(q0 + row) * DK + c16 * 8);
    }
    load_kv(0);
    CP_COMMIT();
    CP_WAIT0();
    __syncthreads();

    // Q fragments (then stages 1/2 become free)
    uint32_t qh[4][4], ql[4][4];
    {
        int r = wid * 16 + (lane & 15);
        uint32_t half = (uint32_t)((lane >> 4) << 4);
#pragma unroll
        for (int kc = 0; kc < 4; kc++) {
            ldsm4(qh[kc], sQh + swz((uint32_t)(r * 128 + kc * 32) + half));
            ldsm4(ql[kc], sQl + swz((uint32_t)(r * 128 + kc * 32) + half));
        }
    }
    __syncthreads();   // all warps done reading Q before stages 1/2 reload

    if (nkt > 1) { load_kv(1); CP_COMMIT(); }
    if (nkt > 2) { load_kv(2); CP_COMMIT(); }

    float o[8][4];
#pragma unroll
    for (int nt = 0; nt < 8; nt++)
#pragma unroll
        for (int q = 0; q < 4; q++) o[nt][q] = 0.f;
    float m0v = -3.0e38f, m1v = -3.0e38f, l0 = 0.f, l1 = 0.f;

    const int rq = q0 + wid * 16 + (lane >> 2);

    for (int kt = 0; kt < nkt; kt++) {
        if (kt > 0) {
            const int rem = nkt - 1 - kt;   // groups newer than kv(kt)
            if (rem >= 2) CP_WAIT2();
            else if (rem == 1) CP_WAIT1();
            else CP_WAIT0();
            __syncthreads();
            if (kt + 2 < nkt) { load_kv(kt + 2); CP_COMMIT(); }
        }

        const uint32_t st = sb + (uint32_t)(kt % 3) * ASTAGE_BYTES;

        // ---- S = (Qh+Ql)·Kh ----
        float s[8][4];
#pragma unroll
        for (int nt = 0; nt < 8; nt++)
#pragma unroll
            for (int q = 0; q < 4; q++) s[nt][q] = 0.f;

        const int nrow = (lane & 7) + ((lane >> 4) << 3);
        const uint32_t koff = (uint32_t)(((lane >> 3) & 1) << 4);
#pragma unroll
        for (int kc = 0; kc < 4; kc++) {
            uint32_t kb[16];
#pragma unroll
            for (int nb = 0; nb < 4; nb++)
                ldsm4(kb + nb * 4, st + swz((uint32_t)((nb * 16 + nrow) * 128 + kc * 32) + koff));
#pragma unroll
            for (int nt = 0; nt < 8; nt++) mma16816(s[nt], qh[kc], &kb[nt * 2]);
#pragma unroll
            for (int nt = 0; nt < 8; nt++) mma16816(s[nt], ql[kc], &kb[nt * 2]);
        }

        // ---- causal mask ----
        if (kt * 64 + 63 > q0 + wid * 16) {
            const int cb = kt * 64 + 2 * (lane & 3);
#pragma unroll
            for (int nt = 0; nt < 8; nt++) {
                int c0 = cb + 8 * nt;
                if (c0     > rq)     s[nt][0] = -1.0e30f;
                if (c0 + 1 > rq)     s[nt][1] = -1.0e30f;
                if (c0     > rq + 8) s[nt][2] = -1.0e30f;
                if (c0 + 1 > rq + 8) s[nt][3] = -1.0e30f;
            }
        }

        // ---- online softmax ----
        float mx0 = -3.0e38f, mx1 = -3.0e38f;
#pragma unroll
        for (int nt = 0; nt < 8; nt++) {
            mx0 = fmaxf(mx0, fmaxf(s[nt][0], s[nt][1]));
            mx1 = fmaxf(mx1, fmaxf(s[nt][2], s[nt][3]));
        }
        mx0 = fmaxf(mx0, __shfl_xor_sync(0xFFFFFFFFu, mx0, 1));
        mx0 = fmaxf(mx0, __shfl_xor_sync(0xFFFFFFFFu, mx0, 2));
        mx1 = fmaxf(mx1, __shfl_xor_sync(0xFFFFFFFFu, mx1, 1));
        mx1 = fmaxf(mx1, __shfl_xor_sync(0xFFFFFFFFu, mx1, 2));
        const float mn0 = fmaxf(m0v, mx0), mn1 = fmaxf(m1v, mx1);
        const float f0 = exp2f_fast(m0v - mn0), f1 = exp2f_fast(m1v - mn1);
        m0v = mn0; m1v = mn1;

        float sum0 = 0.f, sum1 = 0.f;
        uint32_t ph[4][4];
#pragma unroll
        for (int kc = 0; kc < 4; kc++) {
            float e00 = exp2f_fast(s[2*kc][0]   - mn0);
            float e01 = exp2f_fast(s[2*kc][1]   - mn0);
            float e10 = exp2f_fast(s[2*kc][2]   - mn1);
            float e11 = exp2f_fast(s[2*kc][3]   - mn1);
            float e20 = exp2f_fast(s[2*kc+1][0] - mn0);
            float e21 = exp2f_fast(s[2*kc+1][1] - mn0);
            float e30 = exp2f_fast(s[2*kc+1][2] - mn1);
            float e31 = exp2f_fast(s[2*kc+1][3] - mn1);
            sum0 += (e00 + e01) + (e20 + e21);
            sum1 += (e10 + e11) + (e30 + e31);
            ph[kc][0] = pack2(e00, e01);
            ph[kc][1] = pack2(e10, e11);
            ph[kc][2] = pack2(e20, e21);
            ph[kc][3] = pack2(e30, e31);
        }
        sum0 += __shfl_xor_sync(0xFFFFFFFFu, sum0, 1);
        sum0 += __shfl_xor_sync(0xFFFFFFFFu, sum0, 2);
        sum1 += __shfl_xor_sync(0xFFFFFFFFu, sum1, 1);
        sum1 += __shfl_xor_sync(0xFFFFFFFFu, sum1, 2);
        l0 = l0 * f0 + sum0;
        l1 = l1 * f1 + sum1;

#pragma unroll
        for (int nt = 0; nt < 8; nt++) {
            o[nt][0] *= f0; o[nt][1] *= f0;
            o[nt][2] *= f1; o[nt][3] *= f1;
        }

        // ---- O += Ph·Vh ----
        const int vkey = ((lane >> 3) & 1) * 8 + (lane & 7);
        const uint32_t vdk = (uint32_t)(((lane >> 4) << 3) * 2);
#pragma unroll
        for (int kc = 0; kc < 4; kc++) {
            uint32_t vb[16];
#pragma unroll
            for (int p4 = 0; p4 < 4; p4++)
                ldsm4t(vb + p4 * 4, st + 8192 +
                       swz((uint32_t)((kc * 16 + vkey) * 128 + p4 * 32) + vdk));
#pragma unroll
            for (int nt = 0; nt < 8; nt++) mma16816(o[nt], ph[kc], &vb[nt * 2]);
        }
    }

    // ---- epilogue: normalize, store fp16 hi to [B,S,H*DK] ----
    const float inv0 = 1.0f / l0, inv1 = 1.0f / l1;
    const int b = bh >> 4, hd = bh & 15;
    const int dkb = 2 * (lane & 3);
#pragma unroll
    for (int nt = 0; nt < 8; nt++) {
        const int d = hd * 64 + dkb + 8 * nt;
        size_t i0 = ((size_t)b * SEQ + rq) * DMODEL + d;
        size_t i1 = ((size_t)b * SEQ + rq + 8) * DMODEL + d;
        uint32_t p0 = pack2(o[nt][0] * inv0, o[nt][1] * inv0);
        uint32_t p1 = pack2(o[nt][2] * inv1, o[nt][3] * inv1);
        *reinterpret_cast<uint32_t*>(g_ah + i0) = p0;
        *reinterpret_cast<uint32_t*>(g_ah + i1) = p1;
    }
}

// ---------------------------------------------------------------------------
extern "C" void kernel_launch(void* const* d_in, const int* in_sizes, int n_in,
                              void* d_out, int out_size)
{
    const float* x  = (const float*)d_in[0];
    const float* Wq = (const float*)d_in[1];
    const float* bq = (const float*)d_in[2];
    const float* Wk = (const float*)d_in[3];
    const float* bk = (const float*)d_in[4];
    const float* Wv = (const float*)d_in[5];
    const float* bv = (const float*)d_in[6];
    const float* Wo = (const float*)d_in[7];
    const float* bo = (const float*)d_in[8];
    float* out = (float*)d_out;
    (void)in_sizes; (void)n_in; (void)out_size;

    static bool attr_done = false;
    if (!attr_done) {
        cudaFuncSetAttribute(mma_gemm<0>, cudaFuncAttributeMaxDynamicSharedMemorySize, GEMM_SMEM);
        cudaFuncSetAttribute(mma_gemm<1>, cudaFuncAttributeMaxDynamicSharedMemorySize, GEMM_SMEM);
        cudaFuncSetAttribute(attn_mma_kernel, cudaFuncAttributeMaxDynamicSharedMemorySize, ATTN_SMEM);
        attr_done = true;
    }

    split_all_kernel<<<SPLIT_BLOCKS, 256>>>((const float4*)x, (const float4*)Wq,
                                            (const float4*)Wk, (const float4*)Wv,
                                            (const float4*)Wo);

    dim3 gQKV(MTOT / BM, DMODEL / BN, 3);
    mma_gemm<0><<<gQKV, 256, GEMM_SMEM>>>(bq, bk, bv, nullptr);

    dim3 gAttn(SEQ / 128, BATCH * NHEADS);
    attn_mma_kernel<<<gAttn, 256, ATTN_SMEM>>>();

    dim3 gProj(MTOT / BM, DMODEL / BN);
    mma_gemm<1><<<gProj, 256, GEMM_SMEM>>>(bo, nullptr, nullptr, out);
}